// round 9
// baseline (speedup 1.0000x reference)
#include <cuda_runtime.h>
#include <cuda_bf16.h>
#include <math.h>
#include <stdint.h>

#define BB 32768
#define DD 1024
#define KK 512
#define INV_T 10.0f

// ---------------- scratch (static device globals) ----------------------------
__device__ __align__(16) __nv_bfloat16 g_Ss[16777216];   // scores_s bf16
__device__ __align__(16) __nv_bfloat16 g_E[16777216];    // E bf16
__device__ __align__(16) __nv_bfloat16 g_Zb[16777216];   // Z bf16 (unnormalized)
__device__ __align__(16) __nv_bfloat16 g_W[524288];      // W_net bf16
__device__ __align__(16) __nv_bfloat16 g_Cn[262144];     // normalized protos bf16
__device__ float g_ss[BB];      // row sumsq of Z
__device__ float g_invn[BB];    // 1/||Z row||
__device__ float g_R[KK];
__device__ float g_alpha[KK];
__device__ float g_S;
__device__ float g_loss;

// ---------------- helpers ------------------------------------------------------
__device__ __forceinline__ uint32_t smem_u32(const void* p) {
    uint32_t a;
    asm("{ .reg .u64 t; cvta.to.shared.u64 t, %1; cvt.u32.u64 %0, t; }"
        : "=r"(a) : "l"(p));
    return a;
}
__device__ __forceinline__ void cp_async16(uint32_t saddr, const void* g) {
    asm volatile("cp.async.cg.shared.global [%0], [%1], 16;"
                 :: "r"(saddr), "l"(g) : "memory");
}
__device__ __forceinline__ void ldsm_x4(uint32_t* r, uint32_t addr) {
    asm volatile("ldmatrix.sync.aligned.m8n8.x4.shared.b16 {%0,%1,%2,%3}, [%4];"
                 : "=r"(r[0]), "=r"(r[1]), "=r"(r[2]), "=r"(r[3]) : "r"(addr));
}
__device__ __forceinline__ void mma16816(float* c, const uint32_t* a,
                                         uint32_t b0, uint32_t b1) {
    asm volatile(
        "mma.sync.aligned.m16n8k16.row.col.f32.bf16.bf16.f32 "
        "{%0,%1,%2,%3}, {%4,%5,%6,%7}, {%8,%9}, {%0,%1,%2,%3};"
        : "+f"(c[0]), "+f"(c[1]), "+f"(c[2]), "+f"(c[3])
        : "r"(a[0]), "r"(a[1]), "r"(a[2]), "r"(a[3]), "r"(b0), "r"(b1));
}
#define SWZ(o) ((o) ^ (((o) >> 3) & 0x70))

// fast e^x on the FMA pipe (exp2-based, degree-6 poly, rel err ~6e-8)
__device__ __forceinline__ float fexp(float x) {
    float y = x * 1.4426950408889634f;
    float t = y + 12582912.0f;
    int e = __float_as_int(t) - 0x4B400000;
    float f = y - (t - 12582912.0f);
    float p = 1.5403530e-4f;
    p = fmaf(p, f, 1.3333558e-3f);
    p = fmaf(p, f, 9.6181291e-3f);
    p = fmaf(p, f, 5.5504109e-2f);
    p = fmaf(p, f, 2.4022651e-1f);
    p = fmaf(p, f, 6.9314718e-1f);
    p = fmaf(p, f, 1.0f);
    return p * __int_as_float((e + 127) << 23);
}

__device__ __forceinline__ __nv_bfloat162 pack2(float a, float b) {
    return __halves2bfloat162(__float2bfloat16(a), __float2bfloat16(b));
}

// ---------------- init ----------------------------------------------------------
__global__ void k_init() {
    int i = blockIdx.x * blockDim.x + threadIdx.x;
    g_ss[i] = 0.0f;
    if (i < KK) g_R[i] = 0.0f;
    if (i == 0) g_loss = 0.0f;
}

// ---------------- Cn = l2norm rows of W_proto -> bf16 ---------------------------
__global__ void k_proto(const float* __restrict__ W) {
    int row = blockIdx.x;
    int t = threadIdx.x;
    float4 v = ((const float4*)(W + (size_t)row * KK))[t];
    float s = v.x * v.x + v.y * v.y + v.z * v.z + v.w * v.w;
    __shared__ float sm[128];
    sm[t] = s;
    __syncthreads();
    for (int o = 64; o > 0; o >>= 1) {
        if (t < o) sm[t] += sm[t + o];
        __syncthreads();
    }
    float inv = rsqrtf(sm[0]);
    __nv_bfloat162* hp = (__nv_bfloat162*)(g_Cn + (size_t)row * KK + t * 4);
    hp[0] = pack2(v.x * inv, v.y * inv);
    hp[1] = pack2(v.z * inv, v.w * inv);
}

// ---------------- f32 -> bf16 (W_net only; tiny) ----------------------------------
__global__ void k_conv(const float* __restrict__ x, __nv_bfloat16* __restrict__ hd,
                       int n4) {
    int i = blockIdx.x * blockDim.x + threadIdx.x;
    int stride = gridDim.x * blockDim.x;
    for (; i < n4; i += stride) {
        float4 v = ((const float4*)x)[i];
        __nv_bfloat162* hp = (__nv_bfloat162*)(hd + (size_t)i * 4);
        hp[0] = pack2(v.x, v.y);
        hp[1] = pack2(v.z, v.w);
    }
}

// ---------------- invn = rsqrt(ss); ss = 0 ----------------------------------------
__global__ void k_inv() {
    int i = blockIdx.x * blockDim.x + threadIdx.x;
    g_invn[i] = rsqrtf(g_ss[i]);
    g_ss[i] = 0.0f;
}

// ================= gemm1 fused-convert: Zb = bf16(A_f32 @ W^T), sumsq ============
// A: f32 [BB, 1024], converted f32->bf16 IN REGISTERS (LDG.128 -> cvt -> STS.16B).
// smem: Abf[2] 16KB @0, Bt[2] 16KB @32768. One __syncthreads per k-tile.
#define G1_ABF 0
#define G1_BT 32768
#define G1_SMEM 65536
__global__ void __launch_bounds__(256, 2)
k_gemm1f(const float* __restrict__ A, const __nv_bfloat16* __restrict__ B,
         __nv_bfloat16* __restrict__ C) {
    extern __shared__ char smem[];
    const int Kd = DD;          // 1024
    const int NT = Kd >> 6;     // 16 k-tiles

    int tid = threadIdx.x, wid = tid >> 5, lane = tid & 31;
    int m0 = blockIdx.y * 128, n0 = blockIdx.x * 128;
    int wm = wid >> 2, wn = wid & 3;

    uint32_t s_base = smem_u32(smem);

    // --- A register-convert loader: thread owns row r=tid>>1, 32-col half ch ---
    int arow = tid >> 1;
    int ach = (tid & 1) * 32;                   // f32 col offset within 64-col tile
    const float* gA = A + (size_t)(m0 + arow) * Kd + ach;
    // STS targets for the two 16-f32 batches (bytes): row*128 + ach*2 + q*32
    uint32_t stsA0 = SWZ((uint32_t)(arow * 128 + ach * 2));
    uint32_t stsA1 = stsA0 ^ 16u;               // +16B within same 32B group? NO-
    // careful: SWZ(x+16) != SWZ(x)^16 in general; compute both properly:
    uint32_t stsA_q0_0 = SWZ((uint32_t)(arow * 128 + ach * 2 + 0));
    uint32_t stsA_q0_1 = SWZ((uint32_t)(arow * 128 + ach * 2 + 16));
    uint32_t stsA_q1_0 = SWZ((uint32_t)(arow * 128 + ach * 2 + 32));
    uint32_t stsA_q1_1 = SWZ((uint32_t)(arow * 128 + ach * 2 + 48));

    // --- B cp.async loader ---
    int lrow = tid >> 3, lseg = tid & 7;
    const __nv_bfloat16* gB0 = B + (size_t)(n0 + lrow) * Kd + lseg * 8;
    auto loadB = [&](int kt, int st) {
        uint32_t sa = s_base + G1_BT + (uint32_t)st * 16384;
        int kc = kt * 64;
#pragma unroll
        for (int p = 0; p < 4; p++) {
            uint32_t so = SWZ((lrow + p * 32) * 128 + lseg * 16);
            cp_async16(sa + so, gB0 + (size_t)p * 32 * Kd + kc);
        }
        asm volatile("cp.async.commit_group;" ::: "memory");
    };

    // batch LDG (4x float4 = 16 f32), convert, 2x STS.16B
    float4 fb[4];
    auto ldgA = [&](int kt, int q) {
#pragma unroll
        for (int j = 0; j < 4; j++)
            fb[j] = *(const float4*)(gA + kt * 64 + q * 16 + j * 4);
    };
    auto stsA = [&](int st, int q) {
        uint32_t ab = s_base + G1_ABF + (uint32_t)st * 16384;
        __nv_bfloat162 p0 = pack2(fb[0].x, fb[0].y), p1 = pack2(fb[0].z, fb[0].w);
        __nv_bfloat162 p2 = pack2(fb[1].x, fb[1].y), p3 = pack2(fb[1].z, fb[1].w);
        __nv_bfloat162 p4 = pack2(fb[2].x, fb[2].y), p5 = pack2(fb[2].z, fb[2].w);
        __nv_bfloat162 p6 = pack2(fb[3].x, fb[3].y), p7 = pack2(fb[3].z, fb[3].w);
        uint32_t a0 = q ? stsA_q1_0 : stsA_q0_0;
        uint32_t a1 = q ? stsA_q1_1 : stsA_q0_1;
        asm volatile("st.shared.v4.b32 [%0], {%1,%2,%3,%4};"
                     :: "r"(ab + a0), "r"(*(uint32_t*)&p0), "r"(*(uint32_t*)&p1),
                        "r"(*(uint32_t*)&p2), "r"(*(uint32_t*)&p3) : "memory");
        asm volatile("st.shared.v4.b32 [%0], {%1,%2,%3,%4};"
                     :: "r"(ab + a1), "r"(*(uint32_t*)&p4), "r"(*(uint32_t*)&p5),
                        "r"(*(uint32_t*)&p6), "r"(*(uint32_t*)&p7) : "memory");
    };

    // --- ldmatrix offsets (tile-relative) ---
    uint32_t offA[4], offB[2];
    {
        int rA = (lane & 7) + ((lane >> 3) & 1) * 8;
        int sA = (lane >> 4) * 16;
#pragma unroll
        for (int im = 0; im < 4; im++) {
            int row = wm * 64 + im * 16 + rA;
            offA[im] = (uint32_t)(row * 128) | (uint32_t)(sA ^ ((row & 7) << 4));
        }
        int rB = (lane & 7) + ((lane >> 4) & 1) * 8;
        int sB = ((lane >> 3) & 1) * 16;
#pragma unroll
        for (int j = 0; j < 2; j++) {
            int row = wn * 32 + j * 16 + rB;
            offB[j] = (uint32_t)(row * 128) | (uint32_t)(sB ^ ((row & 7) << 4));
        }
    }

    float acc[4][4][4];
#pragma unroll
    for (int i = 0; i < 4; i++)
#pragma unroll
        for (int j = 0; j < 4; j++)
#pragma unroll
            for (int k = 0; k < 4; k++) acc[i][j][k] = 0.0f;

    // --- prologue: fill tile 0 ---
    loadB(0, 0);
    ldgA(0, 0); stsA(0, 0);
    ldgA(0, 1); stsA(0, 1);
    asm volatile("cp.async.wait_group 0;" ::: "memory");
    __syncthreads();

    for (int kt = 0; kt < NT; kt++) {
        int st = kt & 1;
        bool more = (kt + 1 < NT);
        if (more) {
            loadB(kt + 1, st ^ 1);
            ldgA(kt + 1, 0);
        }
        uint32_t sbA = s_base + G1_ABF + (uint32_t)st * 16384;
        uint32_t sbB = s_base + G1_BT + (uint32_t)st * 16384;

        // k-steps 0,1
#pragma unroll
        for (int ks = 0; ks < 2; ks++) {
            uint32_t kx = (uint32_t)(ks << 5);
            uint32_t a[4][4], b[2][4];
#pragma unroll
            for (int im = 0; im < 4; im++) ldsm_x4(a[im], sbA + (offA[im] ^ kx));
#pragma unroll
            for (int j = 0; j < 2; j++) ldsm_x4(b[j], sbB + (offB[j] ^ kx));
#pragma unroll
            for (int im = 0; im < 4; im++)
#pragma unroll
                for (int j = 0; j < 2; j++) {
                    mma16816(acc[im][j * 2 + 0], a[im], b[j][0], b[j][1]);
                    mma16816(acc[im][j * 2 + 1], a[im], b[j][2], b[j][3]);
                }
        }
        if (more) {
            stsA(st ^ 1, 0);
            ldgA(kt + 1, 1);
        }
        // k-steps 2,3
#pragma unroll
        for (int ks = 2; ks < 4; ks++) {
            uint32_t kx = (uint32_t)(ks << 5);
            uint32_t a[4][4], b[2][4];
#pragma unroll
            for (int im = 0; im < 4; im++) ldsm_x4(a[im], sbA + (offA[im] ^ kx));
#pragma unroll
            for (int j = 0; j < 2; j++) ldsm_x4(b[j], sbB + (offB[j] ^ kx));
#pragma unroll
            for (int im = 0; im < 4; im++)
#pragma unroll
                for (int j = 0; j < 2; j++) {
                    mma16816(acc[im][j * 2 + 0], a[im], b[j][0], b[j][1]);
                    mma16816(acc[im][j * 2 + 1], a[im], b[j][2], b[j][3]);
                }
        }
        if (more) {
            stsA(st ^ 1, 1);
            asm volatile("cp.async.wait_group 0;" ::: "memory");
        }
        __syncthreads();
    }

    // ---- epilogue: bf16 out + row sumsq ----
#pragma unroll
    for (int im = 0; im < 4; im++) {
        int m = m0 + wm * 64 + im * 16 + (lane >> 2);
        float s0 = 0.0f, s1 = 0.0f;
#pragma unroll
        for (int jn = 0; jn < 4; jn++) {
            int n = n0 + wn * 32 + jn * 8 + (lane & 3) * 2;
            float c0 = acc[im][jn][0], c1 = acc[im][jn][1];
            float c2 = acc[im][jn][2], c3 = acc[im][jn][3];
            s0 += c0 * c0 + c1 * c1;
            s1 += c2 * c2 + c3 * c3;
            *(__nv_bfloat162*)(C + (size_t)m * KK + n) = pack2(c0, c1);
            *(__nv_bfloat162*)(C + (size_t)(m + 8) * KK + n) = pack2(c2, c3);
        }
        s0 += __shfl_xor_sync(0xffffffffu, s0, 1);
        s0 += __shfl_xor_sync(0xffffffffu, s0, 2);
        s1 += __shfl_xor_sync(0xffffffffu, s1, 1);
        s1 += __shfl_xor_sync(0xffffffffu, s1, 2);
        if ((lane & 3) == 0) {
            atomicAdd(&g_ss[m], s0);
            atomicAdd(&g_ss[m + 8], s1);
        }
    }
}

// ================= gemm2 (bf16 A): scores / E ====================================
// mode 1: out = bf16(acc * invn[m])                              (student)
// mode 2: out = bf16(fexp((acc*invn[m]-1)*10)), colsums -> g_R   (teacher)
#define STAGES 3
#define STAGE_BYTES 32768
__global__ void __launch_bounds__(256, 2)
k_gemm(const __nv_bfloat16* __restrict__ A, const __nv_bfloat16* __restrict__ B,
       __nv_bfloat16* __restrict__ C, int Kd, int mode) {
    extern __shared__ char smem[];
    __shared__ float scp[2][128];

    int tid = threadIdx.x, wid = tid >> 5, lane = tid & 31;
    int m0 = blockIdx.y * 128, n0 = blockIdx.x * 128;
    int wm = wid >> 2, wn = wid & 3;

    uint32_t s_base = smem_u32(smem);
    int NT = Kd >> 6;

    int lrow = tid >> 3, lseg = tid & 7;
    const __nv_bfloat16* gA0 = A + (size_t)(m0 + lrow) * Kd + lseg * 8;
    const __nv_bfloat16* gB0 = B + (size_t)(n0 + lrow) * Kd + lseg * 8;
    auto load = [&](int kt, int st) {
        int kc = kt * 64;
        uint32_t sa = s_base + st * STAGE_BYTES;
#pragma unroll
        for (int p = 0; p < 4; p++) {
            uint32_t so = SWZ((lrow + p * 32) * 128 + lseg * 16);
            cp_async16(sa + so, gA0 + (size_t)p * 32 * Kd + kc);
            cp_async16(sa + 16384 + so, gB0 + (size_t)p * 32 * Kd + kc);
        }
        asm volatile("cp.async.commit_group;" ::: "memory");
    };

    uint32_t offA[4], offB[2];
    {
        int rA = (lane & 7) + ((lane >> 3) & 1) * 8;
        int sA = (lane >> 4) * 16;
#pragma unroll
        for (int im = 0; im < 4; im++) {
            int row = wm * 64 + im * 16 + rA;
            offA[im] = (uint32_t)(row * 128) | (uint32_t)(sA ^ ((row & 7) << 4));
        }
        int rB = (lane & 7) + ((lane >> 4) & 1) * 8;
        int sB = ((lane >> 3) & 1) * 16;
#pragma unroll
        for (int j = 0; j < 2; j++) {
            int row = wn * 32 + j * 16 + rB;
            offB[j] = 16384u + ((uint32_t)(row * 128) |
                                (uint32_t)(sB ^ ((row & 7) << 4)));
        }
    }

    float acc[4][4][4];
#pragma unroll
    for (int i = 0; i < 4; i++)
#pragma unroll
        for (int j = 0; j < 4; j++)
#pragma unroll
            for (int k = 0; k < 4; k++) acc[i][j][k] = 0.0f;

    load(0, 0);
    load(1, 1);

    for (int kt = 0; kt < NT; kt++) {
        asm volatile("cp.async.wait_group 1;" ::: "memory");
        __syncthreads();
        uint32_t sb = s_base + (uint32_t)(kt % 3) * STAGE_BYTES;
#pragma unroll
        for (int ks = 0; ks < 4; ks++) {
            uint32_t kx = (uint32_t)(ks << 5);
            uint32_t a[4][4], b[2][4];
#pragma unroll
            for (int im = 0; im < 4; im++) ldsm_x4(a[im], sb + (offA[im] ^ kx));
#pragma unroll
            for (int j = 0; j < 2; j++) ldsm_x4(b[j], sb + (offB[j] ^ kx));
#pragma unroll
            for (int im = 0; im < 4; im++)
#pragma unroll
                for (int j = 0; j < 2; j++) {
                    mma16816(acc[im][j * 2 + 0], a[im], b[j][0], b[j][1]);
                    mma16816(acc[im][j * 2 + 1], a[im], b[j][2], b[j][3]);
                }
        }
        if (kt + 2 < NT) load(kt + 2, (kt + 2) % 3);
        else asm volatile("cp.async.commit_group;" ::: "memory");
    }

    float ce0[4] = {0, 0, 0, 0}, ce1[4] = {0, 0, 0, 0};
#pragma unroll
    for (int im = 0; im < 4; im++) {
        int m = m0 + wm * 64 + im * 16 + (lane >> 2);
        float i0 = g_invn[m], i1 = g_invn[m + 8];
#pragma unroll
        for (int jn = 0; jn < 4; jn++) {
            int n = n0 + wn * 32 + jn * 8 + (lane & 3) * 2;
            float c0 = acc[im][jn][0] * i0, c1 = acc[im][jn][1] * i0;
            float c2 = acc[im][jn][2] * i1, c3 = acc[im][jn][3] * i1;
            if (mode == 2) {
                c0 = fexp((c0 - 1.0f) * INV_T);
                c1 = fexp((c1 - 1.0f) * INV_T);
                c2 = fexp((c2 - 1.0f) * INV_T);
                c3 = fexp((c3 - 1.0f) * INV_T);
                ce0[jn] += c0 + c2;
                ce1[jn] += c1 + c3;
            }
            *(__nv_bfloat162*)(C + (size_t)m * KK + n) = pack2(c0, c1);
            *(__nv_bfloat162*)(C + (size_t)(m + 8) * KK + n) = pack2(c2, c3);
        }
    }
    if (mode == 2) {
#pragma unroll
        for (int jn = 0; jn < 4; jn++) {
#pragma unroll
            for (int o = 4; o < 32; o <<= 1) {
                ce0[jn] += __shfl_xor_sync(0xffffffffu, ce0[jn], o);
                ce1[jn] += __shfl_xor_sync(0xffffffffu, ce1[jn], o);
            }
        }
        if (lane < 4) {
#pragma unroll
            for (int jn = 0; jn < 4; jn++) {
                scp[wm][wn * 32 + jn * 8 + lane * 2 + 0] = ce0[jn];
                scp[wm][wn * 32 + jn * 8 + lane * 2 + 1] = ce1[jn];
            }
        }
        __syncthreads();
        if (tid < 128)
            atomicAdd(&g_R[n0 + tid], scp[0][tid] + scp[1][tid]);
    }
}

// ---------------- alpha_k = S / (K * R_k), reset R -----------------------------------
__global__ void k_alpha(int first) {
    int t = threadIdx.x;           // 512
    float Rk = g_R[t];
    __shared__ float sm[512];
    float S;
    if (first) {
        sm[t] = Rk;
        __syncthreads();
        for (int o = 256; o > 0; o >>= 1) {
            if (t < o) sm[t] += sm[t + o];
            __syncthreads();
        }
        S = sm[0];
        if (t == 0) g_S = S;
    } else {
        S = g_S;
    }
    g_alpha[t] = S / (512.0f * Rk);
    g_R[t] = 0.0f;
}

// ---------------- fused sinkhorn iteration ------------------------------------------
__global__ void k_rcpass() {
    int wid = threadIdx.x >> 5, lane = threadIdx.x & 31;
    __shared__ float sc[8][512];

    float al[16];
    const float* ap = g_alpha + lane * 16;
#pragma unroll
    for (int j = 0; j < 16; j++) al[j] = ap[j];
    float S = g_S;

    float colp[16];
#pragma unroll
    for (int j = 0; j < 16; j++) colp[j] = 0.0f;

    int row0 = blockIdx.x * 256 + wid * 32;
    for (int r = 0; r < 32; r++) {
        int row = row0 + r;
        const uint4* pe = (const uint4*)(g_E + (size_t)row * KK + lane * 16);
        uint4 u0 = pe[0], u1 = pe[1];
        float ev[16];
        {
            __nv_bfloat162* h0 = (__nv_bfloat162*)&u0;
            __nv_bfloat162* h1 = (__nv_bfloat162*)&u1;
#pragma unroll
            for (int k = 0; k < 4; k++) {
                float2 f0 = __bfloat1622float2(h0[k]);
                float2 f1 = __bfloat1622float2(h1[k]);
                ev[k * 2 + 0] = f0.x; ev[k * 2 + 1] = f0.y;
                ev[8 + k * 2 + 0] = f1.x; ev[8 + k * 2 + 1] = f1.y;
            }
        }
        float dot = 0.0f;
#pragma unroll
        for (int j = 0; j < 16; j++) dot = fmaf(ev[j], al[j], dot);
#pragma unroll
        for (int o = 16; o > 0; o >>= 1) dot += __shfl_xor_sync(0xffffffffu, dot, o);
        float beta = S / (32768.0f * dot);
#pragma unroll
        for (int j = 0; j < 16; j++) colp[j] = fmaf(ev[j], beta, colp[j]);
    }
#pragma unroll
    for (int j = 0; j < 16; j++) sc[wid][lane * 16 + j] = colp[j];
    __syncthreads();
    for (int c = threadIdx.x; c < 512; c += 256) {
        float sum = sc[0][c] + sc[1][c] + sc[2][c] + sc[3][c]
                  + sc[4][c] + sc[5][c] + sc[6][c] + sc[7][c];
        atomicAdd(&g_R[c], sum);
    }
}

// ---------------- fused lse + loss ----------------------------------------------------
__global__ void k_loss() {
    int wid = threadIdx.x >> 5, lane = threadIdx.x & 31;
    __shared__ float sl[8];

    float al[16];
    const float* ap = g_alpha + lane * 16;
#pragma unroll
    for (int j = 0; j < 16; j++) al[j] = ap[j];

    float lacc = 0.0f;
    int row0 = blockIdx.x * 64 + wid * 8;
    for (int r = 0; r < 8; r++) {
        int row = row0 + r;
        const uint4* pe = (const uint4*)(g_E + (size_t)row * KK + lane * 16);
        const uint4* ps = (const uint4*)(g_Ss + (size_t)row * KK + lane * 16);
        uint4 ue0 = pe[0], ue1 = pe[1], us0 = ps[0], us1 = ps[1];
        float ev[16], v[16];
        {
            __nv_bfloat162* he0 = (__nv_bfloat162*)&ue0;
            __nv_bfloat162* he1 = (__nv_bfloat162*)&ue1;
            __nv_bfloat162* hs0 = (__nv_bfloat162*)&us0;
            __nv_bfloat162* hs1 = (__nv_bfloat162*)&us1;
#pragma unroll
            for (int k = 0; k < 4; k++) {
                float2 f0 = __bfloat1622float2(he0[k]);
                float2 f1 = __bfloat1622float2(he1[k]);
                ev[k * 2] = f0.x; ev[k * 2 + 1] = f0.y;
                ev[8 + k * 2] = f1.x; ev[8 + k * 2 + 1] = f1.y;
                float2 g0 = __bfloat1622float2(hs0[k]);
                float2 g1 = __bfloat1622float2(hs1[k]);
                v[k * 2] = g0.x * INV_T; v[k * 2 + 1] = g0.y * INV_T;
                v[8 + k * 2] = g1.x * INV_T; v[8 + k * 2 + 1] = g1.y * INV_T;
            }
        }
        float mx = v[0];
#pragma unroll
        for (int j = 1; j < 16; j++) mx = fmaxf(mx, v[j]);
#pragma unroll
        for (int o = 16; o > 0; o >>= 1)
            mx = fmaxf(mx, __shfl_xor_sync(0xffffffffu, mx, o));
        float se = 0.0f, C = 0.0f, Acc = 0.0f;
#pragma unroll
        for (int j = 0; j < 16; j++) {
            se += fexp(v[j] - mx);
            float q = ev[j] * al[j];
            C += q;
            Acc = fmaf(q, v[j], Acc);
        }
#pragma unroll
        for (int o = 16; o > 0; o >>= 1) {
            se += __shfl_xor_sync(0xffffffffu, se, o);
            C += __shfl_xor_sync(0xffffffffu, C, o);
            Acc += __shfl_xor_sync(0xffffffffu, Acc, o);
        }
        float lse = mx + logf(se);
        lacc += -(Acc - lse * C) / C;
    }
    if (lane == 0) sl[wid] = lacc;
    __syncthreads();
    if (threadIdx.x == 0) {
        float b = sl[0] + sl[1] + sl[2] + sl[3] + sl[4] + sl[5] + sl[6] + sl[7];
        atomicAdd(&g_loss, b);
    }
}

__global__ void k_final(float* __restrict__ out) {
    out[0] = g_loss * (1.0f / 32768.0f);
}

// ---------------- launch ---------------------------------------------------------------
#define GEMM_SMEM (STAGES * STAGE_BYTES)

extern "C" void kernel_launch(void* const* d_in, const int* in_sizes, int n_in,
                              void* d_out, int out_size) {
    const float* s = nullptr;
    const float* t = nullptr;
    const float* W_net = nullptr;
    const float* W_proto = nullptr;
    for (int i = 0; i < n_in; i++) {
        long long sz = in_sizes[i];
        if (sz == (long long)BB * DD) {
            if (!s) s = (const float*)d_in[i];
            else if (!t) t = (const float*)d_in[i];
        } else if (sz == (long long)KK * DD) {
            W_net = (const float*)d_in[i];
        } else if (sz == (long long)KK * KK) {
            W_proto = (const float*)d_in[i];
        }
    }
    float* out = (float*)d_out;

    __nv_bfloat16 *Ss, *E, *Zb, *W, *Cn;
    cudaGetSymbolAddress((void**)&Ss, g_Ss);
    cudaGetSymbolAddress((void**)&E, g_E);
    cudaGetSymbolAddress((void**)&Zb, g_Zb);
    cudaGetSymbolAddress((void**)&W, g_W);
    cudaGetSymbolAddress((void**)&Cn, g_Cn);

    cudaFuncSetAttribute(k_gemm1f, cudaFuncAttributeMaxDynamicSharedMemorySize, G1_SMEM);
    cudaFuncSetAttribute(k_gemm, cudaFuncAttributeMaxDynamicSharedMemorySize, GEMM_SMEM);

    dim3 gg(KK / 128, BB / 128);   // (4, 256)

    k_init<<<BB / 512, 512>>>();
    k_proto<<<KK, 128>>>(W_proto);
    k_conv<<<512, 256>>>(W_net, W, (KK * DD) / 4);

    // student branch: Zb = bf16(s@W^T) + sumsq (reg-fused f32 conv); Ss = bf16(invn*(Zb@Cn^T))
    k_gemm1f<<<gg, 256, G1_SMEM>>>(s, W, Zb);
    k_inv<<<BB / 256, 256>>>();
    k_gemm<<<gg, 256, GEMM_SMEM>>>(Zb, Cn, Ss, KK, 1);

    // teacher branch: E = bf16(fexp((invn*(Zb@Cn^T)-1)*10)), colsums into g_R
    k_gemm1f<<<gg, 256, G1_SMEM>>>(t, W, Zb);
    k_inv<<<BB / 256, 256>>>();
    k_gemm<<<gg, 256, GEMM_SMEM>>>(Zb, Cn, E, KK, 2);

    // sinkhorn (factor form, fused row+col passes)
    k_alpha<<<1, 512>>>(1);
    k_rcpass<<<128, 256>>>();
    k_alpha<<<1, 512>>>(0);
    k_rcpass<<<128, 256>>>();
    k_alpha<<<1, 512>>>(0);

    // fused lse + loss
    k_loss<<<512, 256>>>();
    k_final<<<1, 1>>>(out);
}

// round 10
// speedup vs baseline: 1.3410x; 1.3410x over previous
#include <cuda_runtime.h>
#include <cuda_bf16.h>
#include <math.h>
#include <stdint.h>

#define BB 32768
#define DD 1024
#define KK 512
#define INV_T 10.0f

// ---------------- scratch (static device globals) ----------------------------
__device__ __align__(16) __nv_bfloat16 g_Ss[16777216];   // scores_s bf16
__device__ __align__(16) __nv_bfloat16 g_E[16777216];    // E bf16
__device__ __align__(16) __nv_bfloat16 g_Zb[16777216];   // Z bf16 (unnormalized)
__device__ __align__(16) __nv_bfloat16 g_W[524288];      // W_net bf16
__device__ __align__(16) __nv_bfloat16 g_Cn[262144];     // normalized protos bf16
__device__ float g_ss[BB];      // row sumsq of Z
__device__ float g_invn[BB];    // 1/||Z row||
__device__ float g_R[KK];
__device__ float g_alpha[KK];
__device__ float g_S;
__device__ float g_loss;

// ---------------- helpers ------------------------------------------------------
__device__ __forceinline__ uint32_t smem_u32(const void* p) {
    uint32_t a;
    asm("{ .reg .u64 t; cvta.to.shared.u64 t, %1; cvt.u32.u64 %0, t; }"
        : "=r"(a) : "l"(p));
    return a;
}
__device__ __forceinline__ void cp_async16(uint32_t saddr, const void* g) {
    asm volatile("cp.async.cg.shared.global [%0], [%1], 16;"
                 :: "r"(saddr), "l"(g) : "memory");
}
__device__ __forceinline__ void ldsm_x4(uint32_t* r, uint32_t addr) {
    asm volatile("ldmatrix.sync.aligned.m8n8.x4.shared.b16 {%0,%1,%2,%3}, [%4];"
                 : "=r"(r[0]), "=r"(r[1]), "=r"(r[2]), "=r"(r[3]) : "r"(addr));
}
__device__ __forceinline__ void mma16816(float* c, const uint32_t* a,
                                         uint32_t b0, uint32_t b1) {
    asm volatile(
        "mma.sync.aligned.m16n8k16.row.col.f32.bf16.bf16.f32 "
        "{%0,%1,%2,%3}, {%4,%5,%6,%7}, {%8,%9}, {%0,%1,%2,%3};"
        : "+f"(c[0]), "+f"(c[1]), "+f"(c[2]), "+f"(c[3])
        : "r"(a[0]), "r"(a[1]), "r"(a[2]), "r"(a[3]), "r"(b0), "r"(b1));
}
#define SWZ(o) ((o) ^ (((o) >> 3) & 0x70))

// fast e^x on the FMA pipe (exp2-based, degree-6 poly, rel err ~6e-8)
__device__ __forceinline__ float fexp(float x) {
    float y = x * 1.4426950408889634f;
    float t = y + 12582912.0f;
    int e = __float_as_int(t) - 0x4B400000;
    float f = y - (t - 12582912.0f);
    float p = 1.5403530e-4f;
    p = fmaf(p, f, 1.3333558e-3f);
    p = fmaf(p, f, 9.6181291e-3f);
    p = fmaf(p, f, 5.5504109e-2f);
    p = fmaf(p, f, 2.4022651e-1f);
    p = fmaf(p, f, 6.9314718e-1f);
    p = fmaf(p, f, 1.0f);
    return p * __int_as_float((e + 127) << 23);
}

__device__ __forceinline__ __nv_bfloat162 pack2(float a, float b) {
    return __halves2bfloat162(__float2bfloat16(a), __float2bfloat16(b));
}

// ---------------- init ----------------------------------------------------------
__global__ void k_init() {
    int i = blockIdx.x * blockDim.x + threadIdx.x;
    g_ss[i] = 0.0f;
    if (i < KK) g_R[i] = 0.0f;
    if (i == 0) g_loss = 0.0f;
}

// ---------------- Cn = l2norm rows of W_proto -> bf16 ---------------------------
__global__ void k_proto(const float* __restrict__ W) {
    int row = blockIdx.x;
    int t = threadIdx.x;
    float4 v = ((const float4*)(W + (size_t)row * KK))[t];
    float s = v.x * v.x + v.y * v.y + v.z * v.z + v.w * v.w;
    __shared__ float sm[128];
    sm[t] = s;
    __syncthreads();
    for (int o = 64; o > 0; o >>= 1) {
        if (t < o) sm[t] += sm[t + o];
        __syncthreads();
    }
    float inv = rsqrtf(sm[0]);
    __nv_bfloat162* hp = (__nv_bfloat162*)(g_Cn + (size_t)row * KK + t * 4);
    hp[0] = pack2(v.x * inv, v.y * inv);
    hp[1] = pack2(v.z * inv, v.w * inv);
}

// ---------------- f32 -> bf16 (W_net only; tiny) ----------------------------------
__global__ void k_conv(const float* __restrict__ x, __nv_bfloat16* __restrict__ hd,
                       int n4) {
    int i = blockIdx.x * blockDim.x + threadIdx.x;
    int stride = gridDim.x * blockDim.x;
    for (; i < n4; i += stride) {
        float4 v = ((const float4*)x)[i];
        __nv_bfloat162* hp = (__nv_bfloat162*)(hd + (size_t)i * 4);
        hp[0] = pack2(v.x, v.y);
        hp[1] = pack2(v.z, v.w);
    }
}

// ---------------- invn = rsqrt(ss); ss = 0 ----------------------------------------
__global__ void k_inv() {
    int i = blockIdx.x * blockDim.x + threadIdx.x;
    g_invn[i] = rsqrtf(g_ss[i]);
    g_ss[i] = 0.0f;
}

// ================= gemm1 fused-convert: Zb = bf16(A_f32 @ W^T), sumsq ============
// A: f32 [BB, 1024]. cp.async f32 staging (coalesced 128B rows) -> smem convert
// -> bf16 tile. FULL k-tile convert: 2 barriers/k-tile. Loads issued before MMA.
// smem: Abf[2] 16KB @0, Bt[2] 16KB @32768, Ast(f32, single) 32KB @65536.
#define G1_ABF 0
#define G1_BT 32768
#define G1_AST 65536
#define G1_SMEM 98304
__global__ void __launch_bounds__(256, 2)
k_gemm1f(const float* __restrict__ A, const __nv_bfloat16* __restrict__ B,
         __nv_bfloat16* __restrict__ C) {
    extern __shared__ char smem[];
    const int Kd = DD;          // 1024
    const int NT = Kd >> 6;     // 16 k-tiles

    int tid = threadIdx.x, wid = tid >> 5, lane = tid & 31;
    int m0 = blockIdx.y * 128, n0 = blockIdx.x * 128;
    int wm = wid >> 2, wn = wid & 3;

    uint32_t s_base = smem_u32(smem);

    // --- A staging loader: rows 256B (64 f32), row-XOR swizzle on 16B units ---
    int lrow = tid >> 3, lseg = tid & 7;           // 32 rows, 8 segs x16B
    const float* gA0 = A + (size_t)(m0 + lrow) * Kd + lseg * 4;
    auto loadAst = [&](int kt) {
        uint32_t sa = s_base + G1_AST;
        int kc = kt * 64;
#pragma unroll
        for (int p = 0; p < 4; p++) {
            int row = lrow + p * 32;
            uint32_t rsw = ((uint32_t)(row & 7)) << 4;
#pragma unroll
            for (int h = 0; h < 2; h++) {
                uint32_t off = (uint32_t)(h * 128 + lseg * 16) ^ rsw;
                cp_async16(sa + (uint32_t)row * 256 + off,
                           gA0 + (size_t)p * 32 * Kd + kc + h * 32);
            }
        }
    };

    // --- B cp.async loader (bf16, SW128) ---
    const __nv_bfloat16* gB0 = B + (size_t)(n0 + lrow) * Kd + lseg * 8;
    auto loadB = [&](int kt, int st) {
        uint32_t sa = s_base + G1_BT + (uint32_t)st * 16384;
        int kc = kt * 64;
#pragma unroll
        for (int p = 0; p < 4; p++) {
            uint32_t so = SWZ((lrow + p * 32) * 128 + lseg * 16);
            cp_async16(sa + so, gB0 + (size_t)p * 32 * Kd + kc);
        }
    };

    // --- full-tile convert: staging f32 -> Abf[st] bf16 (SW128) ---
    int crow = tid >> 1, chalf = tid & 1;          // 128 rows x 2 halves(32 f32)
    uint32_t crbase = (uint32_t)crow * 256;
    uint32_t crsw = ((uint32_t)(crow & 7)) << 4;
    auto convertA = [&](int st) {
        uint32_t stg = s_base + G1_AST;
        uint32_t abf = s_base + G1_ABF + (uint32_t)st * 16384;
#pragma unroll
        for (int q = 0; q < 4; q++) {
            float4 f0, f1;
            uint32_t o0 = (uint32_t)(chalf * 128 + q * 32);
            asm volatile("ld.shared.v4.f32 {%0,%1,%2,%3}, [%4];"
                         : "=f"(f0.x), "=f"(f0.y), "=f"(f0.z), "=f"(f0.w)
                         : "r"(stg + crbase + (o0 ^ crsw)));
            asm volatile("ld.shared.v4.f32 {%0,%1,%2,%3}, [%4];"
                         : "=f"(f1.x), "=f"(f1.y), "=f"(f1.z), "=f"(f1.w)
                         : "r"(stg + crbase + ((o0 + 16) ^ crsw)));
            __nv_bfloat162 p0 = pack2(f0.x, f0.y), p1 = pack2(f0.z, f0.w);
            __nv_bfloat162 p2 = pack2(f1.x, f1.y), p3 = pack2(f1.z, f1.w);
            asm volatile("st.shared.v4.b32 [%0], {%1,%2,%3,%4};"
                         :: "r"(abf + SWZ((uint32_t)(crow * 128 + chalf * 64 + q * 16))),
                            "r"(*(uint32_t*)&p0), "r"(*(uint32_t*)&p1),
                            "r"(*(uint32_t*)&p2), "r"(*(uint32_t*)&p3) : "memory");
        }
    };

    // --- ldmatrix offsets (tile-relative) ---
    uint32_t offA[4], offB[2];
    {
        int rA = (lane & 7) + ((lane >> 3) & 1) * 8;
        int sA = (lane >> 4) * 16;
#pragma unroll
        for (int im = 0; im < 4; im++) {
            int row = wm * 64 + im * 16 + rA;
            offA[im] = (uint32_t)(row * 128) | (uint32_t)(sA ^ ((row & 7) << 4));
        }
        int rB = (lane & 7) + ((lane >> 4) & 1) * 8;
        int sB = ((lane >> 3) & 1) * 16;
#pragma unroll
        for (int j = 0; j < 2; j++) {
            int row = wn * 32 + j * 16 + rB;
            offB[j] = (uint32_t)(row * 128) | (uint32_t)(sB ^ ((row & 7) << 4));
        }
    }

    float acc[4][4][4];
#pragma unroll
    for (int i = 0; i < 4; i++)
#pragma unroll
        for (int j = 0; j < 4; j++)
#pragma unroll
            for (int k = 0; k < 4; k++) acc[i][j][k] = 0.0f;

    // --- prologue: tile 0 ---
    loadB(0, 0);
    loadAst(0);
    asm volatile("cp.async.commit_group;" ::: "memory");
    asm volatile("cp.async.wait_group 0;" ::: "memory");
    __syncthreads();
    convertA(0);
    __syncthreads();

    for (int kt = 0; kt < NT; kt++) {
        int st = kt & 1;
        bool more = (kt + 1 < NT);
        if (more) {
            // staging(kt) fully converted at the barrier above -> safe to refill
            loadB(kt + 1, st ^ 1);
            loadAst(kt + 1);
            asm volatile("cp.async.commit_group;" ::: "memory");
        }
        uint32_t sbA = s_base + G1_ABF + (uint32_t)st * 16384;
        uint32_t sbB = s_base + G1_BT + (uint32_t)st * 16384;
#pragma unroll
        for (int ks = 0; ks < 4; ks++) {
            uint32_t kx = (uint32_t)(ks << 5);
            uint32_t a[4][4], b[2][4];
#pragma unroll
            for (int im = 0; im < 4; im++) ldsm_x4(a[im], sbA + (offA[im] ^ kx));
#pragma unroll
            for (int j = 0; j < 2; j++) ldsm_x4(b[j], sbB + (offB[j] ^ kx));
#pragma unroll
            for (int im = 0; im < 4; im++)
#pragma unroll
                for (int j = 0; j < 2; j++) {
                    mma16816(acc[im][j * 2 + 0], a[im], b[j][0], b[j][1]);
                    mma16816(acc[im][j * 2 + 1], a[im], b[j][2], b[j][3]);
                }
        }
        if (more) {
            asm volatile("cp.async.wait_group 0;" ::: "memory");
            __syncthreads();
            convertA(st ^ 1);
            __syncthreads();
        }
    }

    // ---- epilogue: bf16 out + row sumsq ----
#pragma unroll
    for (int im = 0; im < 4; im++) {
        int m = m0 + wm * 64 + im * 16 + (lane >> 2);
        float s0 = 0.0f, s1 = 0.0f;
#pragma unroll
        for (int jn = 0; jn < 4; jn++) {
            int n = n0 + wn * 32 + jn * 8 + (lane & 3) * 2;
            float c0 = acc[im][jn][0], c1 = acc[im][jn][1];
            float c2 = acc[im][jn][2], c3 = acc[im][jn][3];
            s0 += c0 * c0 + c1 * c1;
            s1 += c2 * c2 + c3 * c3;
            *(__nv_bfloat162*)(C + (size_t)m * KK + n) = pack2(c0, c1);
            *(__nv_bfloat162*)(C + (size_t)(m + 8) * KK + n) = pack2(c2, c3);
        }
        s0 += __shfl_xor_sync(0xffffffffu, s0, 1);
        s0 += __shfl_xor_sync(0xffffffffu, s0, 2);
        s1 += __shfl_xor_sync(0xffffffffu, s1, 1);
        s1 += __shfl_xor_sync(0xffffffffu, s1, 2);
        if ((lane & 3) == 0) {
            atomicAdd(&g_ss[m], s0);
            atomicAdd(&g_ss[m + 8], s1);
        }
    }
}

// ================= gemm2 (bf16 A): scores / E ====================================
// mode 1: out = bf16(acc * invn[m])                              (student)
// mode 2: out = bf16(fexp((acc*invn[m]-1)*10)), colsums -> g_R   (teacher)
#define STAGES 3
#define STAGE_BYTES 32768
__global__ void __launch_bounds__(256, 2)
k_gemm(const __nv_bfloat16* __restrict__ A, const __nv_bfloat16* __restrict__ B,
       __nv_bfloat16* __restrict__ C, int Kd, int mode) {
    extern __shared__ char smem[];
    __shared__ float scp[2][128];

    int tid = threadIdx.x, wid = tid >> 5, lane = tid & 31;
    int m0 = blockIdx.y * 128, n0 = blockIdx.x * 128;
    int wm = wid >> 2, wn = wid & 3;

    uint32_t s_base = smem_u32(smem);
    int NT = Kd >> 6;

    int lrow = tid >> 3, lseg = tid & 7;
    const __nv_bfloat16* gA0 = A + (size_t)(m0 + lrow) * Kd + lseg * 8;
    const __nv_bfloat16* gB0 = B + (size_t)(n0 + lrow) * Kd + lseg * 8;
    auto load = [&](int kt, int st) {
        int kc = kt * 64;
        uint32_t sa = s_base + st * STAGE_BYTES;
#pragma unroll
        for (int p = 0; p < 4; p++) {
            uint32_t so = SWZ((lrow + p * 32) * 128 + lseg * 16);
            cp_async16(sa + so, gA0 + (size_t)p * 32 * Kd + kc);
            cp_async16(sa + 16384 + so, gB0 + (size_t)p * 32 * Kd + kc);
        }
        asm volatile("cp.async.commit_group;" ::: "memory");
    };

    uint32_t offA[4], offB[2];
    {
        int rA = (lane & 7) + ((lane >> 3) & 1) * 8;
        int sA = (lane >> 4) * 16;
#pragma unroll
        for (int im = 0; im < 4; im++) {
            int row = wm * 64 + im * 16 + rA;
            offA[im] = (uint32_t)(row * 128) | (uint32_t)(sA ^ ((row & 7) << 4));
        }
        int rB = (lane & 7) + ((lane >> 4) & 1) * 8;
        int sB = ((lane >> 3) & 1) * 16;
#pragma unroll
        for (int j = 0; j < 2; j++) {
            int row = wn * 32 + j * 16 + rB;
            offB[j] = 16384u + ((uint32_t)(row * 128) |
                                (uint32_t)(sB ^ ((row & 7) << 4)));
        }
    }

    float acc[4][4][4];
#pragma unroll
    for (int i = 0; i < 4; i++)
#pragma unroll
        for (int j = 0; j < 4; j++)
#pragma unroll
            for (int k = 0; k < 4; k++) acc[i][j][k] = 0.0f;

    load(0, 0);
    load(1, 1);

    for (int kt = 0; kt < NT; kt++) {
        asm volatile("cp.async.wait_group 1;" ::: "memory");
        __syncthreads();
        uint32_t sb = s_base + (uint32_t)(kt % 3) * STAGE_BYTES;
#pragma unroll
        for (int ks = 0; ks < 4; ks++) {
            uint32_t kx = (uint32_t)(ks << 5);
            uint32_t a[4][4], b[2][4];
#pragma unroll
            for (int im = 0; im < 4; im++) ldsm_x4(a[im], sb + (offA[im] ^ kx));
#pragma unroll
            for (int j = 0; j < 2; j++) ldsm_x4(b[j], sb + (offB[j] ^ kx));
#pragma unroll
            for (int im = 0; im < 4; im++)
#pragma unroll
                for (int j = 0; j < 2; j++) {
                    mma16816(acc[im][j * 2 + 0], a[im], b[j][0], b[j][1]);
                    mma16816(acc[im][j * 2 + 1], a[im], b[j][2], b[j][3]);
                }
        }
        if (kt + 2 < NT) load(kt + 2, (kt + 2) % 3);
        else asm volatile("cp.async.commit_group;" ::: "memory");
    }

    float ce0[4] = {0, 0, 0, 0}, ce1[4] = {0, 0, 0, 0};
#pragma unroll
    for (int im = 0; im < 4; im++) {
        int m = m0 + wm * 64 + im * 16 + (lane >> 2);
        float i0 = g_invn[m], i1 = g_invn[m + 8];
#pragma unroll
        for (int jn = 0; jn < 4; jn++) {
            int n = n0 + wn * 32 + jn * 8 + (lane & 3) * 2;
            float c0 = acc[im][jn][0] * i0, c1 = acc[im][jn][1] * i0;
            float c2 = acc[im][jn][2] * i1, c3 = acc[im][jn][3] * i1;
            if (mode == 2) {
                c0 = fexp((c0 - 1.0f) * INV_T);
                c1 = fexp((c1 - 1.0f) * INV_T);
                c2 = fexp((c2 - 1.0f) * INV_T);
                c3 = fexp((c3 - 1.0f) * INV_T);
                ce0[jn] += c0 + c2;
                ce1[jn] += c1 + c3;
            }
            *(__nv_bfloat162*)(C + (size_t)m * KK + n) = pack2(c0, c1);
            *(__nv_bfloat162*)(C + (size_t)(m + 8) * KK + n) = pack2(c2, c3);
        }
    }
    if (mode == 2) {
#pragma unroll
        for (int jn = 0; jn < 4; jn++) {
#pragma unroll
            for (int o = 4; o < 32; o <<= 1) {
                ce0[jn] += __shfl_xor_sync(0xffffffffu, ce0[jn], o);
                ce1[jn] += __shfl_xor_sync(0xffffffffu, ce1[jn], o);
            }
        }
        if (lane < 4) {
#pragma unroll
            for (int jn = 0; jn < 4; jn++) {
                scp[wm][wn * 32 + jn * 8 + lane * 2 + 0] = ce0[jn];
                scp[wm][wn * 32 + jn * 8 + lane * 2 + 1] = ce1[jn];
            }
        }
        __syncthreads();
        if (tid < 128)
            atomicAdd(&g_R[n0 + tid], scp[0][tid] + scp[1][tid]);
    }
}

// ---------------- alpha_k = S / (K * R_k), reset R -----------------------------------
__global__ void k_alpha(int first) {
    int t = threadIdx.x;           // 512
    float Rk = g_R[t];
    __shared__ float sm[512];
    float S;
    if (first) {
        sm[t] = Rk;
        __syncthreads();
        for (int o = 256; o > 0; o >>= 1) {
            if (t < o) sm[t] += sm[t + o];
            __syncthreads();
        }
        S = sm[0];
        if (t == 0) g_S = S;
    } else {
        S = g_S;
    }
    g_alpha[t] = S / (512.0f * Rk);
    g_R[t] = 0.0f;
}

// ---------------- fused sinkhorn iteration ------------------------------------------
__global__ void k_rcpass() {
    int wid = threadIdx.x >> 5, lane = threadIdx.x & 31;
    __shared__ float sc[8][512];

    float al[16];
    const float* ap = g_alpha + lane * 16;
#pragma unroll
    for (int j = 0; j < 16; j++) al[j] = ap[j];
    float S = g_S;

    float colp[16];
#pragma unroll
    for (int j = 0; j < 16; j++) colp[j] = 0.0f;

    int row0 = blockIdx.x * 256 + wid * 32;
    for (int r = 0; r < 32; r++) {
        int row = row0 + r;
        const uint4* pe = (const uint4*)(g_E + (size_t)row * KK + lane * 16);
        uint4 u0 = pe[0], u1 = pe[1];
        float ev[16];
        {
            __nv_bfloat162* h0 = (__nv_bfloat162*)&u0;
            __nv_bfloat162* h1 = (__nv_bfloat162*)&u1;
#pragma unroll
            for (int k = 0; k < 4; k++) {
                float2 f0 = __bfloat1622float2(h0[k]);
                float2 f1 = __bfloat1622float2(h1[k]);
                ev[k * 2 + 0] = f0.x; ev[k * 2 + 1] = f0.y;
                ev[8 + k * 2 + 0] = f1.x; ev[8 + k * 2 + 1] = f1.y;
            }
        }
        float dot = 0.0f;
#pragma unroll
        for (int j = 0; j < 16; j++) dot = fmaf(ev[j], al[j], dot);
#pragma unroll
        for (int o = 16; o > 0; o >>= 1) dot += __shfl_xor_sync(0xffffffffu, dot, o);
        float beta = S / (32768.0f * dot);
#pragma unroll
        for (int j = 0; j < 16; j++) colp[j] = fmaf(ev[j], beta, colp[j]);
    }
#pragma unroll
    for (int j = 0; j < 16; j++) sc[wid][lane * 16 + j] = colp[j];
    __syncthreads();
    for (int c = threadIdx.x; c < 512; c += 256) {
        float sum = sc[0][c] + sc[1][c] + sc[2][c] + sc[3][c]
                  + sc[4][c] + sc[5][c] + sc[6][c] + sc[7][c];
        atomicAdd(&g_R[c], sum);
    }
}

// ---------------- fused lse + loss ----------------------------------------------------
__global__ void k_loss() {
    int wid = threadIdx.x >> 5, lane = threadIdx.x & 31;
    __shared__ float sl[8];

    float al[16];
    const float* ap = g_alpha + lane * 16;
#pragma unroll
    for (int j = 0; j < 16; j++) al[j] = ap[j];

    float lacc = 0.0f;
    int row0 = blockIdx.x * 64 + wid * 8;
    for (int r = 0; r < 8; r++) {
        int row = row0 + r;
        const uint4* pe = (const uint4*)(g_E + (size_t)row * KK + lane * 16);
        const uint4* ps = (const uint4*)(g_Ss + (size_t)row * KK + lane * 16);
        uint4 ue0 = pe[0], ue1 = pe[1], us0 = ps[0], us1 = ps[1];
        float ev[16], v[16];
        {
            __nv_bfloat162* he0 = (__nv_bfloat162*)&ue0;
            __nv_bfloat162* he1 = (__nv_bfloat162*)&ue1;
            __nv_bfloat162* hs0 = (__nv_bfloat162*)&us0;
            __nv_bfloat162* hs1 = (__nv_bfloat162*)&us1;
#pragma unroll
            for (int k = 0; k < 4; k++) {
                float2 f0 = __bfloat1622float2(he0[k]);
                float2 f1 = __bfloat1622float2(he1[k]);
                ev[k * 2] = f0.x; ev[k * 2 + 1] = f0.y;
                ev[8 + k * 2] = f1.x; ev[8 + k * 2 + 1] = f1.y;
                float2 g0 = __bfloat1622float2(hs0[k]);
                float2 g1 = __bfloat1622float2(hs1[k]);
                v[k * 2] = g0.x * INV_T; v[k * 2 + 1] = g0.y * INV_T;
                v[8 + k * 2] = g1.x * INV_T; v[8 + k * 2 + 1] = g1.y * INV_T;
            }
        }
        float mx = v[0];
#pragma unroll
        for (int j = 1; j < 16; j++) mx = fmaxf(mx, v[j]);
#pragma unroll
        for (int o = 16; o > 0; o >>= 1)
            mx = fmaxf(mx, __shfl_xor_sync(0xffffffffu, mx, o));
        float se = 0.0f, C = 0.0f, Acc = 0.0f;
#pragma unroll
        for (int j = 0; j < 16; j++) {
            se += fexp(v[j] - mx);
            float q = ev[j] * al[j];
            C += q;
            Acc = fmaf(q, v[j], Acc);
        }
#pragma unroll
        for (int o = 16; o > 0; o >>= 1) {
            se += __shfl_xor_sync(0xffffffffu, se, o);
            C += __shfl_xor_sync(0xffffffffu, C, o);
            Acc += __shfl_xor_sync(0xffffffffu, Acc, o);
        }
        float lse = mx + logf(se);
        lacc += -(Acc - lse * C) / C;
    }
    if (lane == 0) sl[wid] = lacc;
    __syncthreads();
    if (threadIdx.x == 0) {
        float b = sl[0] + sl[1] + sl[2] + sl[3] + sl[4] + sl[5] + sl[6] + sl[7];
        atomicAdd(&g_loss, b);
    }
}

__global__ void k_final(float* __restrict__ out) {
    out[0] = g_loss * (1.0f / 32768.0f);
}

// ---------------- launch ---------------------------------------------------------------
#define GEMM_SMEM (STAGES * STAGE_BYTES)

extern "C" void kernel_launch(void* const* d_in, const int* in_sizes, int n_in,
                              void* d_out, int out_size) {
    const float* s = nullptr;
    const float* t = nullptr;
    const float* W_net = nullptr;
    const float* W_proto = nullptr;
    for (int i = 0; i < n_in; i++) {
        long long sz = in_sizes[i];
        if (sz == (long long)BB * DD) {
            if (!s) s = (const float*)d_in[i];
            else if (!t) t = (const float*)d_in[i];
        } else if (sz == (long long)KK * DD) {
            W_net = (const float*)d_in[i];
        } else if (sz == (long long)KK * KK) {
            W_proto = (const float*)d_in[i];
        }
    }
    float* out = (float*)d_out;

    __nv_bfloat16 *Ss, *E, *Zb, *W, *Cn;
    cudaGetSymbolAddress((void**)&Ss, g_Ss);
    cudaGetSymbolAddress((void**)&E, g_E);
    cudaGetSymbolAddress((void**)&Zb, g_Zb);
    cudaGetSymbolAddress((void**)&W, g_W);
    cudaGetSymbolAddress((void**)&Cn, g_Cn);

    cudaFuncSetAttribute(k_gemm1f, cudaFuncAttributeMaxDynamicSharedMemorySize, G1_SMEM);
    cudaFuncSetAttribute(k_gemm, cudaFuncAttributeMaxDynamicSharedMemorySize, GEMM_SMEM);

    dim3 gg(KK / 128, BB / 128);   // (4, 256)

    k_init<<<BB / 512, 512>>>();
    k_proto<<<KK, 128>>>(W_proto);
    k_conv<<<512, 256>>>(W_net, W, (KK * DD) / 4);

    // student branch: Zb = bf16(s@W^T) + sumsq (fused f32 conv); Ss = bf16(invn*(Zb@Cn^T))
    k_gemm1f<<<gg, 256, G1_SMEM>>>(s, W, Zb);
    k_inv<<<BB / 256, 256>>>();
    k_gemm<<<gg, 256, GEMM_SMEM>>>(Zb, Cn, Ss, KK, 1);

    // teacher branch: E = bf16(fexp((invn*(Zb@Cn^T)-1)*10)), colsums into g_R
    k_gemm1f<<<gg, 256, G1_SMEM>>>(t, W, Zb);
    k_inv<<<BB / 256, 256>>>();
    k_gemm<<<gg, 256, GEMM_SMEM>>>(Zb, Cn, E, KK, 2);

    // sinkhorn (factor form, fused row+col passes)
    k_alpha<<<1, 512>>>(1);
    k_rcpass<<<128, 256>>>();
    k_alpha<<<1, 512>>>(0);
    k_rcpass<<<128, 256>>>();
    k_alpha<<<1, 512>>>(0);

    // fused lse + loss
    k_loss<<<512, 256>>>();
    k_final<<<1, 1>>>(out);
}

// round 11
// speedup vs baseline: 1.3964x; 1.0413x over previous
#include <cuda_runtime.h>
#include <cuda_bf16.h>
#include <math.h>
#include <stdint.h>

#define BB 32768
#define DD 1024
#define KK 512
#define INV_T 10.0f

// ---------------- scratch (static device globals) ----------------------------
__device__ __align__(16) __nv_bfloat16 g_Ss[16777216];   // scores_s bf16
__device__ __align__(16) __nv_bfloat16 g_E[16777216];    // E bf16
__device__ __align__(16) __nv_bfloat16 g_Zb[16777216];   // Z bf16 (unnormalized)
__device__ __align__(16) __nv_bfloat16 g_W[524288];      // W_net bf16
__device__ __align__(16) __nv_bfloat16 g_Cn[262144];     // normalized protos bf16
__device__ float g_ss[BB];      // row sumsq of Z
__device__ float g_invn[BB];    // 1/||Z row||
__device__ float g_R[KK];
__device__ float g_alpha[KK];
__device__ float g_S;
__device__ float g_loss;

// ---------------- helpers ------------------------------------------------------
__device__ __forceinline__ uint32_t smem_u32(const void* p) {
    uint32_t a;
    asm("{ .reg .u64 t; cvta.to.shared.u64 t, %1; cvt.u32.u64 %0, t; }"
        : "=r"(a) : "l"(p));
    return a;
}
__device__ __forceinline__ void cp_async16(uint32_t saddr, const void* g) {
    asm volatile("cp.async.cg.shared.global [%0], [%1], 16;"
                 :: "r"(saddr), "l"(g) : "memory");
}
__device__ __forceinline__ void ldsm_x4(uint32_t* r, uint32_t addr) {
    asm volatile("ldmatrix.sync.aligned.m8n8.x4.shared.b16 {%0,%1,%2,%3}, [%4];"
                 : "=r"(r[0]), "=r"(r[1]), "=r"(r[2]), "=r"(r[3]) : "r"(addr));
}
__device__ __forceinline__ void mma16816(float* c, const uint32_t* a,
                                         uint32_t b0, uint32_t b1) {
    asm volatile(
        "mma.sync.aligned.m16n8k16.row.col.f32.bf16.bf16.f32 "
        "{%0,%1,%2,%3}, {%4,%5,%6,%7}, {%8,%9}, {%0,%1,%2,%3};"
        : "+f"(c[0]), "+f"(c[1]), "+f"(c[2]), "+f"(c[3])
        : "r"(a[0]), "r"(a[1]), "r"(a[2]), "r"(a[3]), "r"(b0), "r"(b1));
}
#define SWZ(o) ((o) ^ (((o) >> 3) & 0x70))

// fast e^x on the FMA pipe (exp2-based, degree-6 poly, rel err ~6e-8)
__device__ __forceinline__ float fexp(float x) {
    float y = x * 1.4426950408889634f;
    float t = y + 12582912.0f;
    int e = __float_as_int(t) - 0x4B400000;
    float f = y - (t - 12582912.0f);
    float p = 1.5403530e-4f;
    p = fmaf(p, f, 1.3333558e-3f);
    p = fmaf(p, f, 9.6181291e-3f);
    p = fmaf(p, f, 5.5504109e-2f);
    p = fmaf(p, f, 2.4022651e-1f);
    p = fmaf(p, f, 6.9314718e-1f);
    p = fmaf(p, f, 1.0f);
    return p * __int_as_float((e + 127) << 23);
}

__device__ __forceinline__ __nv_bfloat162 pack2(float a, float b) {
    return __halves2bfloat162(__float2bfloat16(a), __float2bfloat16(b));
}

// ---------------- init ----------------------------------------------------------
__global__ void k_init() {
    int i = blockIdx.x * blockDim.x + threadIdx.x;
    g_ss[i] = 0.0f;
    if (i < KK) g_R[i] = 0.0f;
    if (i == 0) g_loss = 0.0f;
}

// ---------------- Cn = l2norm rows of W_proto -> bf16 ---------------------------
__global__ void k_proto(const float* __restrict__ W) {
    int row = blockIdx.x;
    int t = threadIdx.x;
    float4 v = ((const float4*)(W + (size_t)row * KK))[t];
    float s = v.x * v.x + v.y * v.y + v.z * v.z + v.w * v.w;
    __shared__ float sm[128];
    sm[t] = s;
    __syncthreads();
    for (int o = 64; o > 0; o >>= 1) {
        if (t < o) sm[t] += sm[t + o];
        __syncthreads();
    }
    float inv = rsqrtf(sm[0]);
    __nv_bfloat162* hp = (__nv_bfloat162*)(g_Cn + (size_t)row * KK + t * 4);
    hp[0] = pack2(v.x * inv, v.y * inv);
    hp[1] = pack2(v.z * inv, v.w * inv);
}

// ---------------- f32 -> bf16 (W_net only; tiny) ----------------------------------
__global__ void k_conv(const float* __restrict__ x, __nv_bfloat16* __restrict__ hd,
                       int n4) {
    int i = blockIdx.x * blockDim.x + threadIdx.x;
    int stride = gridDim.x * blockDim.x;
    for (; i < n4; i += stride) {
        float4 v = ((const float4*)x)[i];
        __nv_bfloat162* hp = (__nv_bfloat162*)(hd + (size_t)i * 4);
        hp[0] = pack2(v.x, v.y);
        hp[1] = pack2(v.z, v.w);
    }
}

// ---------------- invn = rsqrt(ss); ss = 0 ----------------------------------------
__global__ void k_inv() {
    int i = blockIdx.x * blockDim.x + threadIdx.x;
    g_invn[i] = rsqrtf(g_ss[i]);
    g_ss[i] = 0.0f;
}

// ================= gemm1 fused-convert: Zb = bf16(A_f32 @ W^T), sumsq ============
// A f32 loaded with the cp.async COALESCED pattern (warp = 4 rows x 8 segs of 16B,
// 4 lines/LDG) as plain LDG.128 -> register cvt -> STS.8B into the swizzled bf16
// tile. No f32 staging, no extra barrier. smem: Abf[2] 16KB @0, Bt[2] 16KB @32768.
#define G1_ABF 0
#define G1_BT 32768
#define G1_SMEM 65536
__global__ void __launch_bounds__(256, 2)
k_gemm1f(const float* __restrict__ A, const __nv_bfloat16* __restrict__ B,
         __nv_bfloat16* __restrict__ C) {
    extern __shared__ char smem[];
    const int Kd = DD;          // 1024
    const int NT = Kd >> 6;     // 16 k-tiles

    int tid = threadIdx.x, wid = tid >> 5, lane = tid & 31;
    int m0 = blockIdx.y * 128, n0 = blockIdx.x * 128;
    int wm = wid >> 2, wn = wid & 3;

    uint32_t s_base = smem_u32(smem);

    // --- loader mapping (identical to cp.async pattern): 32 rows x 8 segs ---
    int lrow = tid >> 3, lseg = tid & 7;
    const float* gA0 = A + (size_t)(m0 + lrow) * Kd + lseg * 4;   // 16B = 4 f32
    const __nv_bfloat16* gB0 = B + (size_t)(n0 + lrow) * Kd + lseg * 8;

    auto loadB = [&](int kt, int st) {
        uint32_t sa = s_base + G1_BT + (uint32_t)st * 16384;
        int kc = kt * 64;
#pragma unroll
        for (int p = 0; p < 4; p++) {
            uint32_t so = SWZ((lrow + p * 32) * 128 + lseg * 16);
            cp_async16(sa + so, gB0 + (size_t)p * 32 * Kd + kc);
        }
        asm volatile("cp.async.commit_group;" ::: "memory");
    };

    // A: LDG.128 f32 (coalesced) -> cvt -> STS.8B swizzled
    float4 fb[4];
    auto ldgA = [&](int kt, int h) {       // h selects f32 cols [h*32, h*32+32)
#pragma unroll
        for (int p = 0; p < 4; p++)
            fb[p] = *(const float4*)(gA0 + (size_t)p * 32 * Kd + kt * 64 + h * 32);
    };
    uint32_t stsAddr[4][2];
#pragma unroll
    for (int p = 0; p < 4; p++)
#pragma unroll
        for (int h = 0; h < 2; h++)
            stsAddr[p][h] = SWZ((uint32_t)((lrow + p * 32) * 128 + lseg * 8 + h * 64));
    auto stsA = [&](int st, int h) {
        uint32_t ab = s_base + G1_ABF + (uint32_t)st * 16384;
#pragma unroll
        for (int p = 0; p < 4; p++) {
            __nv_bfloat162 q0 = pack2(fb[p].x, fb[p].y);
            __nv_bfloat162 q1 = pack2(fb[p].z, fb[p].w);
            asm volatile("st.shared.v2.b32 [%0], {%1,%2};"
                         :: "r"(ab + stsAddr[p][h]),
                            "r"(*(uint32_t*)&q0), "r"(*(uint32_t*)&q1) : "memory");
        }
    };

    // --- ldmatrix offsets (tile-relative) ---
    uint32_t offA[4], offB[2];
    {
        int rA = (lane & 7) + ((lane >> 3) & 1) * 8;
        int sA = (lane >> 4) * 16;
#pragma unroll
        for (int im = 0; im < 4; im++) {
            int row = wm * 64 + im * 16 + rA;
            offA[im] = (uint32_t)(row * 128) | (uint32_t)(sA ^ ((row & 7) << 4));
        }
        int rB = (lane & 7) + ((lane >> 4) & 1) * 8;
        int sB = ((lane >> 3) & 1) * 16;
#pragma unroll
        for (int j = 0; j < 2; j++) {
            int row = wn * 32 + j * 16 + rB;
            offB[j] = (uint32_t)(row * 128) | (uint32_t)(sB ^ ((row & 7) << 4));
        }
    }

    float acc[4][4][4];
#pragma unroll
    for (int i = 0; i < 4; i++)
#pragma unroll
        for (int j = 0; j < 4; j++)
#pragma unroll
            for (int k = 0; k < 4; k++) acc[i][j][k] = 0.0f;

    // --- prologue: tile 0 ---
    loadB(0, 0);
    ldgA(0, 0); stsA(0, 0);
    ldgA(0, 1); stsA(0, 1);
    asm volatile("cp.async.wait_group 0;" ::: "memory");
    __syncthreads();

    for (int kt = 0; kt < NT; kt++) {
        int st = kt & 1;
        bool more = (kt + 1 < NT);
        if (more) {
            loadB(kt + 1, st ^ 1);
            ldgA(kt + 1, 0);               // LDG in flight over ks0-1
        }
        uint32_t sbA = s_base + G1_ABF + (uint32_t)st * 16384;
        uint32_t sbB = s_base + G1_BT + (uint32_t)st * 16384;
#pragma unroll
        for (int ks = 0; ks < 2; ks++) {
            uint32_t kx = (uint32_t)(ks << 5);
            uint32_t a[4][4], b[2][4];
#pragma unroll
            for (int im = 0; im < 4; im++) ldsm_x4(a[im], sbA + (offA[im] ^ kx));
#pragma unroll
            for (int j = 0; j < 2; j++) ldsm_x4(b[j], sbB + (offB[j] ^ kx));
#pragma unroll
            for (int im = 0; im < 4; im++)
#pragma unroll
                for (int j = 0; j < 2; j++) {
                    mma16816(acc[im][j * 2 + 0], a[im], b[j][0], b[j][1]);
                    mma16816(acc[im][j * 2 + 1], a[im], b[j][2], b[j][3]);
                }
        }
        if (more) {
            stsA(st ^ 1, 0);               // write buffer st^1 (free since kt-1's barrier)
            ldgA(kt + 1, 1);               // LDG in flight over ks2-3
        }
#pragma unroll
        for (int ks = 2; ks < 4; ks++) {
            uint32_t kx = (uint32_t)(ks << 5);
            uint32_t a[4][4], b[2][4];
#pragma unroll
            for (int im = 0; im < 4; im++) ldsm_x4(a[im], sbA + (offA[im] ^ kx));
#pragma unroll
            for (int j = 0; j < 2; j++) ldsm_x4(b[j], sbB + (offB[j] ^ kx));
#pragma unroll
            for (int im = 0; im < 4; im++)
#pragma unroll
                for (int j = 0; j < 2; j++) {
                    mma16816(acc[im][j * 2 + 0], a[im], b[j][0], b[j][1]);
                    mma16816(acc[im][j * 2 + 1], a[im], b[j][2], b[j][3]);
                }
        }
        if (more) {
            stsA(st ^ 1, 1);
            asm volatile("cp.async.wait_group 0;" ::: "memory");
        }
        __syncthreads();
    }

    // ---- epilogue: bf16 out + row sumsq ----
#pragma unroll
    for (int im = 0; im < 4; im++) {
        int m = m0 + wm * 64 + im * 16 + (lane >> 2);
        float s0 = 0.0f, s1 = 0.0f;
#pragma unroll
        for (int jn = 0; jn < 4; jn++) {
            int n = n0 + wn * 32 + jn * 8 + (lane & 3) * 2;
            float c0 = acc[im][jn][0], c1 = acc[im][jn][1];
            float c2 = acc[im][jn][2], c3 = acc[im][jn][3];
            s0 += c0 * c0 + c1 * c1;
            s1 += c2 * c2 + c3 * c3;
            *(__nv_bfloat162*)(C + (size_t)m * KK + n) = pack2(c0, c1);
            *(__nv_bfloat162*)(C + (size_t)(m + 8) * KK + n) = pack2(c2, c3);
        }
        s0 += __shfl_xor_sync(0xffffffffu, s0, 1);
        s0 += __shfl_xor_sync(0xffffffffu, s0, 2);
        s1 += __shfl_xor_sync(0xffffffffu, s1, 1);
        s1 += __shfl_xor_sync(0xffffffffu, s1, 2);
        if ((lane & 3) == 0) {
            atomicAdd(&g_ss[m], s0);
            atomicAdd(&g_ss[m + 8], s1);
        }
    }
}

// ================= gemm2 (bf16 A): scores / E ====================================
// mode 1: out = bf16(acc * invn[m])                              (student)
// mode 2: out = bf16(fexp((acc*invn[m]-1)*10)), colsums -> g_R   (teacher)
#define STAGES 3
#define STAGE_BYTES 32768
__global__ void __launch_bounds__(256, 2)
k_gemm(const __nv_bfloat16* __restrict__ A, const __nv_bfloat16* __restrict__ B,
       __nv_bfloat16* __restrict__ C, int Kd, int mode) {
    extern __shared__ char smem[];
    __shared__ float scp[2][128];

    int tid = threadIdx.x, wid = tid >> 5, lane = tid & 31;
    int m0 = blockIdx.y * 128, n0 = blockIdx.x * 128;
    int wm = wid >> 2, wn = wid & 3;

    uint32_t s_base = smem_u32(smem);
    int NT = Kd >> 6;

    int lrow = tid >> 3, lseg = tid & 7;
    const __nv_bfloat16* gA0 = A + (size_t)(m0 + lrow) * Kd + lseg * 8;
    const __nv_bfloat16* gB0 = B + (size_t)(n0 + lrow) * Kd + lseg * 8;
    auto load = [&](int kt, int st) {
        int kc = kt * 64;
        uint32_t sa = s_base + st * STAGE_BYTES;
#pragma unroll
        for (int p = 0; p < 4; p++) {
            uint32_t so = SWZ((lrow + p * 32) * 128 + lseg * 16);
            cp_async16(sa + so, gA0 + (size_t)p * 32 * Kd + kc);
            cp_async16(sa + 16384 + so, gB0 + (size_t)p * 32 * Kd + kc);
        }
        asm volatile("cp.async.commit_group;" ::: "memory");
    };

    uint32_t offA[4], offB[2];
    {
        int rA = (lane & 7) + ((lane >> 3) & 1) * 8;
        int sA = (lane >> 4) * 16;
#pragma unroll
        for (int im = 0; im < 4; im++) {
            int row = wm * 64 + im * 16 + rA;
            offA[im] = (uint32_t)(row * 128) | (uint32_t)(sA ^ ((row & 7) << 4));
        }
        int rB = (lane & 7) + ((lane >> 4) & 1) * 8;
        int sB = ((lane >> 3) & 1) * 16;
#pragma unroll
        for (int j = 0; j < 2; j++) {
            int row = wn * 32 + j * 16 + rB;
            offB[j] = 16384u + ((uint32_t)(row * 128) |
                                (uint32_t)(sB ^ ((row & 7) << 4)));
        }
    }

    float acc[4][4][4];
#pragma unroll
    for (int i = 0; i < 4; i++)
#pragma unroll
        for (int j = 0; j < 4; j++)
#pragma unroll
            for (int k = 0; k < 4; k++) acc[i][j][k] = 0.0f;

    load(0, 0);
    load(1, 1);

    for (int kt = 0; kt < NT; kt++) {
        asm volatile("cp.async.wait_group 1;" ::: "memory");
        __syncthreads();
        uint32_t sb = s_base + (uint32_t)(kt % 3) * STAGE_BYTES;
#pragma unroll
        for (int ks = 0; ks < 4; ks++) {
            uint32_t kx = (uint32_t)(ks << 5);
            uint32_t a[4][4], b[2][4];
#pragma unroll
            for (int im = 0; im < 4; im++) ldsm_x4(a[im], sb + (offA[im] ^ kx));
#pragma unroll
            for (int j = 0; j < 2; j++) ldsm_x4(b[j], sb + (offB[j] ^ kx));
#pragma unroll
            for (int im = 0; im < 4; im++)
#pragma unroll
                for (int j = 0; j < 2; j++) {
                    mma16816(acc[im][j * 2 + 0], a[im], b[j][0], b[j][1]);
                    mma16816(acc[im][j * 2 + 1], a[im], b[j][2], b[j][3]);
                }
        }
        if (kt + 2 < NT) load(kt + 2, (kt + 2) % 3);
        else asm volatile("cp.async.commit_group;" ::: "memory");
    }

    float ce0[4] = {0, 0, 0, 0}, ce1[4] = {0, 0, 0, 0};
#pragma unroll
    for (int im = 0; im < 4; im++) {
        int m = m0 + wm * 64 + im * 16 + (lane >> 2);
        float i0 = g_invn[m], i1 = g_invn[m + 8];
#pragma unroll
        for (int jn = 0; jn < 4; jn++) {
            int n = n0 + wn * 32 + jn * 8 + (lane & 3) * 2;
            float c0 = acc[im][jn][0] * i0, c1 = acc[im][jn][1] * i0;
            float c2 = acc[im][jn][2] * i1, c3 = acc[im][jn][3] * i1;
            if (mode == 2) {
                c0 = fexp((c0 - 1.0f) * INV_T);
                c1 = fexp((c1 - 1.0f) * INV_T);
                c2 = fexp((c2 - 1.0f) * INV_T);
                c3 = fexp((c3 - 1.0f) * INV_T);
                ce0[jn] += c0 + c2;
                ce1[jn] += c1 + c3;
            }
            *(__nv_bfloat162*)(C + (size_t)m * KK + n) = pack2(c0, c1);
            *(__nv_bfloat162*)(C + (size_t)(m + 8) * KK + n) = pack2(c2, c3);
        }
    }
    if (mode == 2) {
#pragma unroll
        for (int jn = 0; jn < 4; jn++) {
#pragma unroll
            for (int o = 4; o < 32; o <<= 1) {
                ce0[jn] += __shfl_xor_sync(0xffffffffu, ce0[jn], o);
                ce1[jn] += __shfl_xor_sync(0xffffffffu, ce1[jn], o);
            }
        }
        if (lane < 4) {
#pragma unroll
            for (int jn = 0; jn < 4; jn++) {
                scp[wm][wn * 32 + jn * 8 + lane * 2 + 0] = ce0[jn];
                scp[wm][wn * 32 + jn * 8 + lane * 2 + 1] = ce1[jn];
            }
        }
        __syncthreads();
        if (tid < 128)
            atomicAdd(&g_R[n0 + tid], scp[0][tid] + scp[1][tid]);
    }
}

// ---------------- alpha_k = S / (K * R_k), reset R -----------------------------------
__global__ void k_alpha(int first) {
    int t = threadIdx.x;           // 512
    float Rk = g_R[t];
    __shared__ float sm[512];
    float S;
    if (first) {
        sm[t] = Rk;
        __syncthreads();
        for (int o = 256; o > 0; o >>= 1) {
            if (t < o) sm[t] += sm[t + o];
            __syncthreads();
        }
        S = sm[0];
        if (t == 0) g_S = S;
    } else {
        S = g_S;
    }
    g_alpha[t] = S / (512.0f * Rk);
    g_R[t] = 0.0f;
}

// ---------------- fused sinkhorn iteration ------------------------------------------
__global__ void k_rcpass() {
    int wid = threadIdx.x >> 5, lane = threadIdx.x & 31;
    __shared__ float sc[8][512];

    float al[16];
    const float* ap = g_alpha + lane * 16;
#pragma unroll
    for (int j = 0; j < 16; j++) al[j] = ap[j];
    float S = g_S;

    float colp[16];
#pragma unroll
    for (int j = 0; j < 16; j++) colp[j] = 0.0f;

    int row0 = blockIdx.x * 256 + wid * 32;
    for (int r = 0; r < 32; r++) {
        int row = row0 + r;
        const uint4* pe = (const uint4*)(g_E + (size_t)row * KK + lane * 16);
        uint4 u0 = pe[0], u1 = pe[1];
        float ev[16];
        {
            __nv_bfloat162* h0 = (__nv_bfloat162*)&u0;
            __nv_bfloat162* h1 = (__nv_bfloat162*)&u1;
#pragma unroll
            for (int k = 0; k < 4; k++) {
                float2 f0 = __bfloat1622float2(h0[k]);
                float2 f1 = __bfloat1622float2(h1[k]);
                ev[k * 2 + 0] = f0.x; ev[k * 2 + 1] = f0.y;
                ev[8 + k * 2 + 0] = f1.x; ev[8 + k * 2 + 1] = f1.y;
            }
        }
        float dot = 0.0f;
#pragma unroll
        for (int j = 0; j < 16; j++) dot = fmaf(ev[j], al[j], dot);
#pragma unroll
        for (int o = 16; o > 0; o >>= 1) dot += __shfl_xor_sync(0xffffffffu, dot, o);
        float beta = S / (32768.0f * dot);
#pragma unroll
        for (int j = 0; j < 16; j++) colp[j] = fmaf(ev[j], beta, colp[j]);
    }
#pragma unroll
    for (int j = 0; j < 16; j++) sc[wid][lane * 16 + j] = colp[j];
    __syncthreads();
    for (int c = threadIdx.x; c < 512; c += 256) {
        float sum = sc[0][c] + sc[1][c] + sc[2][c] + sc[3][c]
                  + sc[4][c] + sc[5][c] + sc[6][c] + sc[7][c];
        atomicAdd(&g_R[c], sum);
    }
}

// ---------------- fused lse + loss ----------------------------------------------------
__global__ void k_loss() {
    int wid = threadIdx.x >> 5, lane = threadIdx.x & 31;
    __shared__ float sl[8];

    float al[16];
    const float* ap = g_alpha + lane * 16;
#pragma unroll
    for (int j = 0; j < 16; j++) al[j] = ap[j];

    float lacc = 0.0f;
    int row0 = blockIdx.x * 64 + wid * 8;
    for (int r = 0; r < 8; r++) {
        int row = row0 + r;
        const uint4* pe = (const uint4*)(g_E + (size_t)row * KK + lane * 16);
        const uint4* ps = (const uint4*)(g_Ss + (size_t)row * KK + lane * 16);
        uint4 ue0 = pe[0], ue1 = pe[1], us0 = ps[0], us1 = ps[1];
        float ev[16], v[16];
        {
            __nv_bfloat162* he0 = (__nv_bfloat162*)&ue0;
            __nv_bfloat162* he1 = (__nv_bfloat162*)&ue1;
            __nv_bfloat162* hs0 = (__nv_bfloat162*)&us0;
            __nv_bfloat162* hs1 = (__nv_bfloat162*)&us1;
#pragma unroll
            for (int k = 0; k < 4; k++) {
                float2 f0 = __bfloat1622float2(he0[k]);
                float2 f1 = __bfloat1622float2(he1[k]);
                ev[k * 2] = f0.x; ev[k * 2 + 1] = f0.y;
                ev[8 + k * 2] = f1.x; ev[8 + k * 2 + 1] = f1.y;
                float2 g0 = __bfloat1622float2(hs0[k]);
                float2 g1 = __bfloat1622float2(hs1[k]);
                v[k * 2] = g0.x * INV_T; v[k * 2 + 1] = g0.y * INV_T;
                v[8 + k * 2] = g1.x * INV_T; v[8 + k * 2 + 1] = g1.y * INV_T;
            }
        }
        float mx = v[0];
#pragma unroll
        for (int j = 1; j < 16; j++) mx = fmaxf(mx, v[j]);
#pragma unroll
        for (int o = 16; o > 0; o >>= 1)
            mx = fmaxf(mx, __shfl_xor_sync(0xffffffffu, mx, o));
        float se = 0.0f, C = 0.0f, Acc = 0.0f;
#pragma unroll
        for (int j = 0; j < 16; j++) {
            se += fexp(v[j] - mx);
            float q = ev[j] * al[j];
            C += q;
            Acc = fmaf(q, v[j], Acc);
        }
#pragma unroll
        for (int o = 16; o > 0; o >>= 1) {
            se += __shfl_xor_sync(0xffffffffu, se, o);
            C += __shfl_xor_sync(0xffffffffu, C, o);
            Acc += __shfl_xor_sync(0xffffffffu, Acc, o);
        }
        float lse = mx + logf(se);
        lacc += -(Acc - lse * C) / C;
    }
    if (lane == 0) sl[wid] = lacc;
    __syncthreads();
    if (threadIdx.x == 0) {
        float b = sl[0] + sl[1] + sl[2] + sl[3] + sl[4] + sl[5] + sl[6] + sl[7];
        atomicAdd(&g_loss, b);
    }
}

__global__ void k_final(float* __restrict__ out) {
    out[0] = g_loss * (1.0f / 32768.0f);
}

// ---------------- launch ---------------------------------------------------------------
#define GEMM_SMEM (STAGES * STAGE_BYTES)

extern "C" void kernel_launch(void* const* d_in, const int* in_sizes, int n_in,
                              void* d_out, int out_size) {
    const float* s = nullptr;
    const float* t = nullptr;
    const float* W_net = nullptr;
    const float* W_proto = nullptr;
    for (int i = 0; i < n_in; i++) {
        long long sz = in_sizes[i];
        if (sz == (long long)BB * DD) {
            if (!s) s = (const float*)d_in[i];
            else if (!t) t = (const float*)d_in[i];
        } else if (sz == (long long)KK * DD) {
            W_net = (const float*)d_in[i];
        } else if (sz == (long long)KK * KK) {
            W_proto = (const float*)d_in[i];
        }
    }
    float* out = (float*)d_out;

    __nv_bfloat16 *Ss, *E, *Zb, *W, *Cn;
    cudaGetSymbolAddress((void**)&Ss, g_Ss);
    cudaGetSymbolAddress((void**)&E, g_E);
    cudaGetSymbolAddress((void**)&Zb, g_Zb);
    cudaGetSymbolAddress((void**)&W, g_W);
    cudaGetSymbolAddress((void**)&Cn, g_Cn);

    cudaFuncSetAttribute(k_gemm1f, cudaFuncAttributeMaxDynamicSharedMemorySize, G1_SMEM);
    cudaFuncSetAttribute(k_gemm, cudaFuncAttributeMaxDynamicSharedMemorySize, GEMM_SMEM);

    dim3 gg(KK / 128, BB / 128);   // (4, 256)

    k_init<<<BB / 512, 512>>>();
    k_proto<<<KK, 128>>>(W_proto);
    k_conv<<<512, 256>>>(W_net, W, (KK * DD) / 4);

    // student branch: Zb = bf16(s@W^T) + sumsq (reg-convert, coalesced); Ss = bf16(invn*(Zb@Cn^T))
    k_gemm1f<<<gg, 256, G1_SMEM>>>(s, W, Zb);
    k_inv<<<BB / 256, 256>>>();
    k_gemm<<<gg, 256, GEMM_SMEM>>>(Zb, Cn, Ss, KK, 1);

    // teacher branch: E = bf16(fexp((invn*(Zb@Cn^T)-1)*10)), colsums into g_R
    k_gemm1f<<<gg, 256, G1_SMEM>>>(t, W, Zb);
    k_inv<<<BB / 256, 256>>>();
    k_gemm<<<gg, 256, GEMM_SMEM>>>(Zb, Cn, E, KK, 2);

    // sinkhorn (factor form, fused row+col passes)
    k_alpha<<<1, 512>>>(1);
    k_rcpass<<<128, 256>>>();
    k_alpha<<<1, 512>>>(0);
    k_rcpass<<<128, 256>>>();
    k_alpha<<<1, 512>>>(0);

    // fused lse + loss
    k_loss<<<512, 256>>>();
    k_final<<<1, 1>>>(out);
}

// round 12
// speedup vs baseline: 1.5171x; 1.0865x over previous
#include <cuda_runtime.h>
#include <cuda_bf16.h>
#include <math.h>
#include <stdint.h>

#define BB 32768
#define DD 1024
#define KK 512
#define INV_T 10.0f

// ---------------- scratch (static device globals) ----------------------------
__device__ __align__(16) __nv_bfloat16 g_Ss[16777216];   // scores_s bf16
__device__ __align__(16) __nv_bfloat16 g_E[16777216];    // E bf16
__device__ __align__(16) __nv_bfloat16 g_Zb[33554432];   // Z bf16 (s rows 0..32767, t rows 32768..65535)
__device__ __align__(16) __nv_bfloat16 g_W[524288];      // W_net bf16
__device__ __align__(16) __nv_bfloat16 g_Cn[262144];     // normalized protos bf16
__device__ float g_ss[2 * BB];      // row sumsq of Z (both branches)
__device__ float g_invn[2 * BB];    // 1/||Z row||
__device__ float g_R[KK];
__device__ float g_alpha[KK];
__device__ float g_S;
__device__ float g_loss;

// ---------------- helpers ------------------------------------------------------
__device__ __forceinline__ uint32_t smem_u32(const void* p) {
    uint32_t a;
    asm("{ .reg .u64 t; cvta.to.shared.u64 t, %1; cvt.u32.u64 %0, t; }"
        : "=r"(a) : "l"(p));
    return a;
}
__device__ __forceinline__ void cp_async16(uint32_t saddr, const void* g) {
    asm volatile("cp.async.cg.shared.global [%0], [%1], 16;"
                 :: "r"(saddr), "l"(g) : "memory");
}
__device__ __forceinline__ void ldsm_x4(uint32_t* r, uint32_t addr) {
    asm volatile("ldmatrix.sync.aligned.m8n8.x4.shared.b16 {%0,%1,%2,%3}, [%4];"
                 : "=r"(r[0]), "=r"(r[1]), "=r"(r[2]), "=r"(r[3]) : "r"(addr));
}
__device__ __forceinline__ void mma16816(float* c, const uint32_t* a,
                                         uint32_t b0, uint32_t b1) {
    asm volatile(
        "mma.sync.aligned.m16n8k16.row.col.f32.bf16.bf16.f32 "
        "{%0,%1,%2,%3}, {%4,%5,%6,%7}, {%8,%9}, {%0,%1,%2,%3};"
        : "+f"(c[0]), "+f"(c[1]), "+f"(c[2]), "+f"(c[3])
        : "r"(a[0]), "r"(a[1]), "r"(a[2]), "r"(a[3]), "r"(b0), "r"(b1));
}
#define SWZ(o) ((o) ^ (((o) >> 3) & 0x70))

// fast e^x on the FMA pipe (exp2-based, degree-6 poly, rel err ~6e-8)
__device__ __forceinline__ float fexp(float x) {
    float y = x * 1.4426950408889634f;
    float t = y + 12582912.0f;
    int e = __float_as_int(t) - 0x4B400000;
    float f = y - (t - 12582912.0f);
    float p = 1.5403530e-4f;
    p = fmaf(p, f, 1.3333558e-3f);
    p = fmaf(p, f, 9.6181291e-3f);
    p = fmaf(p, f, 5.5504109e-2f);
    p = fmaf(p, f, 2.4022651e-1f);
    p = fmaf(p, f, 6.9314718e-1f);
    p = fmaf(p, f, 1.0f);
    return p * __int_as_float((e + 127) << 23);
}

__device__ __forceinline__ __nv_bfloat162 pack2(float a, float b) {
    return __halves2bfloat162(__float2bfloat16(a), __float2bfloat16(b));
}

// ---------------- init ----------------------------------------------------------
__global__ void k_init() {
    int i = blockIdx.x * blockDim.x + threadIdx.x;     // 65536 threads
    g_ss[i] = 0.0f;
    if (i < KK) g_R[i] = 0.0f;
    if (i == 0) g_loss = 0.0f;
}

// ---------------- Cn = l2norm rows of W_proto -> bf16 ---------------------------
__global__ void k_proto(const float* __restrict__ W) {
    int row = blockIdx.x;
    int t = threadIdx.x;
    float4 v = ((const float4*)(W + (size_t)row * KK))[t];
    float s = v.x * v.x + v.y * v.y + v.z * v.z + v.w * v.w;
    __shared__ float sm[128];
    sm[t] = s;
    __syncthreads();
    for (int o = 64; o > 0; o >>= 1) {
        if (t < o) sm[t] += sm[t + o];
        __syncthreads();
    }
    float inv = rsqrtf(sm[0]);
    __nv_bfloat162* hp = (__nv_bfloat162*)(g_Cn + (size_t)row * KK + t * 4);
    hp[0] = pack2(v.x * inv, v.y * inv);
    hp[1] = pack2(v.z * inv, v.w * inv);
}

// ---------------- f32 -> bf16 (W_net only; tiny) ----------------------------------
__global__ void k_conv(const float* __restrict__ x, __nv_bfloat16* __restrict__ hd,
                       int n4) {
    int i = blockIdx.x * blockDim.x + threadIdx.x;
    int stride = gridDim.x * blockDim.x;
    for (; i < n4; i += stride) {
        float4 v = ((const float4*)x)[i];
        __nv_bfloat162* hp = (__nv_bfloat162*)(hd + (size_t)i * 4);
        hp[0] = pack2(v.x, v.y);
        hp[1] = pack2(v.z, v.w);
    }
}

// ---------------- invn = rsqrt(ss); (both branches) --------------------------------
__global__ void k_inv() {
    int i = blockIdx.x * blockDim.x + threadIdx.x;
    g_invn[i] = rsqrtf(g_ss[i]);
}

// ================= gemm1 batched: Zb[0:B) = s@W^T, Zb[B:2B) = t@W^T ==============
// grid.y = 512: blocks 0..255 read s, 256..511 read t. Register f32->bf16 convert.
#define G1_ABF 0
#define G1_BT 32768
#define G1_SMEM 65536
__global__ void __launch_bounds__(256, 2)
k_gemm1f(const float* __restrict__ S, const float* __restrict__ T,
         const __nv_bfloat16* __restrict__ B, __nv_bfloat16* __restrict__ C) {
    extern __shared__ char smem[];
    const int Kd = DD;          // 1024
    const int NT = Kd >> 6;     // 16 k-tiles

    int tid = threadIdx.x, wid = tid >> 5, lane = tid & 31;
    int by = blockIdx.y;
    const float* A = (by < 256) ? S : T;
    int am0 = (by & 255) * 128;            // row in source tensor
    int m0 = by * 128;                     // global row (C, g_ss)
    int n0 = blockIdx.x * 128;
    int wm = wid >> 2, wn = wid & 3;

    uint32_t s_base = smem_u32(smem);

    int lrow = tid >> 3, lseg = tid & 7;
    const float* gA0 = A + (size_t)(am0 + lrow) * Kd + lseg * 4;
    const __nv_bfloat16* gB0 = B + (size_t)(n0 + lrow) * Kd + lseg * 8;

    auto loadB = [&](int kt, int st) {
        uint32_t sa = s_base + G1_BT + (uint32_t)st * 16384;
        int kc = kt * 64;
#pragma unroll
        for (int p = 0; p < 4; p++) {
            uint32_t so = SWZ((lrow + p * 32) * 128 + lseg * 16);
            cp_async16(sa + so, gB0 + (size_t)p * 32 * Kd + kc);
        }
        asm volatile("cp.async.commit_group;" ::: "memory");
    };

    float4 fb[4];
    auto ldgA = [&](int kt, int h) {
#pragma unroll
        for (int p = 0; p < 4; p++)
            fb[p] = *(const float4*)(gA0 + (size_t)p * 32 * Kd + kt * 64 + h * 32);
    };
    uint32_t stsAddr[4][2];
#pragma unroll
    for (int p = 0; p < 4; p++)
#pragma unroll
        for (int h = 0; h < 2; h++)
            stsAddr[p][h] = SWZ((uint32_t)((lrow + p * 32) * 128 + lseg * 8 + h * 64));
    auto stsA = [&](int st, int h) {
        uint32_t ab = s_base + G1_ABF + (uint32_t)st * 16384;
#pragma unroll
        for (int p = 0; p < 4; p++) {
            __nv_bfloat162 q0 = pack2(fb[p].x, fb[p].y);
            __nv_bfloat162 q1 = pack2(fb[p].z, fb[p].w);
            asm volatile("st.shared.v2.b32 [%0], {%1,%2};"
                         :: "r"(ab + stsAddr[p][h]),
                            "r"(*(uint32_t*)&q0), "r"(*(uint32_t*)&q1) : "memory");
        }
    };

    uint32_t offA[4], offB[2];
    {
        int rA = (lane & 7) + ((lane >> 3) & 1) * 8;
        int sA = (lane >> 4) * 16;
#pragma unroll
        for (int im = 0; im < 4; im++) {
            int row = wm * 64 + im * 16 + rA;
            offA[im] = (uint32_t)(row * 128) | (uint32_t)(sA ^ ((row & 7) << 4));
        }
        int rB = (lane & 7) + ((lane >> 4) & 1) * 8;
        int sB = ((lane >> 3) & 1) * 16;
#pragma unroll
        for (int j = 0; j < 2; j++) {
            int row = wn * 32 + j * 16 + rB;
            offB[j] = (uint32_t)(row * 128) | (uint32_t)(sB ^ ((row & 7) << 4));
        }
    }

    float acc[4][4][4];
#pragma unroll
    for (int i = 0; i < 4; i++)
#pragma unroll
        for (int j = 0; j < 4; j++)
#pragma unroll
            for (int k = 0; k < 4; k++) acc[i][j][k] = 0.0f;

    loadB(0, 0);
    ldgA(0, 0); stsA(0, 0);
    ldgA(0, 1); stsA(0, 1);
    asm volatile("cp.async.wait_group 0;" ::: "memory");
    __syncthreads();

    for (int kt = 0; kt < NT; kt++) {
        int st = kt & 1;
        bool more = (kt + 1 < NT);
        if (more) {
            loadB(kt + 1, st ^ 1);
            ldgA(kt + 1, 0);
        }
        uint32_t sbA = s_base + G1_ABF + (uint32_t)st * 16384;
        uint32_t sbB = s_base + G1_BT + (uint32_t)st * 16384;
#pragma unroll
        for (int ks = 0; ks < 2; ks++) {
            uint32_t kx = (uint32_t)(ks << 5);
            uint32_t a[4][4], b[2][4];
#pragma unroll
            for (int im = 0; im < 4; im++) ldsm_x4(a[im], sbA + (offA[im] ^ kx));
#pragma unroll
            for (int j = 0; j < 2; j++) ldsm_x4(b[j], sbB + (offB[j] ^ kx));
#pragma unroll
            for (int im = 0; im < 4; im++)
#pragma unroll
                for (int j = 0; j < 2; j++) {
                    mma16816(acc[im][j * 2 + 0], a[im], b[j][0], b[j][1]);
                    mma16816(acc[im][j * 2 + 1], a[im], b[j][2], b[j][3]);
                }
        }
        if (more) {
            stsA(st ^ 1, 0);
            ldgA(kt + 1, 1);
        }
#pragma unroll
        for (int ks = 2; ks < 4; ks++) {
            uint32_t kx = (uint32_t)(ks << 5);
            uint32_t a[4][4], b[2][4];
#pragma unroll
            for (int im = 0; im < 4; im++) ldsm_x4(a[im], sbA + (offA[im] ^ kx));
#pragma unroll
            for (int j = 0; j < 2; j++) ldsm_x4(b[j], sbB + (offB[j] ^ kx));
#pragma unroll
            for (int im = 0; im < 4; im++)
#pragma unroll
                for (int j = 0; j < 2; j++) {
                    mma16816(acc[im][j * 2 + 0], a[im], b[j][0], b[j][1]);
                    mma16816(acc[im][j * 2 + 1], a[im], b[j][2], b[j][3]);
                }
        }
        if (more) {
            stsA(st ^ 1, 1);
            asm volatile("cp.async.wait_group 0;" ::: "memory");
        }
        __syncthreads();
    }

    // ---- epilogue: bf16 out + row sumsq ----
#pragma unroll
    for (int im = 0; im < 4; im++) {
        int m = m0 + wm * 64 + im * 16 + (lane >> 2);
        float s0 = 0.0f, s1 = 0.0f;
#pragma unroll
        for (int jn = 0; jn < 4; jn++) {
            int n = n0 + wn * 32 + jn * 8 + (lane & 3) * 2;
            float c0 = acc[im][jn][0], c1 = acc[im][jn][1];
            float c2 = acc[im][jn][2], c3 = acc[im][jn][3];
            s0 += c0 * c0 + c1 * c1;
            s1 += c2 * c2 + c3 * c3;
            *(__nv_bfloat162*)(C + (size_t)m * KK + n) = pack2(c0, c1);
            *(__nv_bfloat162*)(C + (size_t)(m + 8) * KK + n) = pack2(c2, c3);
        }
        s0 += __shfl_xor_sync(0xffffffffu, s0, 1);
        s0 += __shfl_xor_sync(0xffffffffu, s0, 2);
        s1 += __shfl_xor_sync(0xffffffffu, s1, 1);
        s1 += __shfl_xor_sync(0xffffffffu, s1, 2);
        if ((lane & 3) == 0) {
            atomicAdd(&g_ss[m], s0);
            atomicAdd(&g_ss[m + 8], s1);
        }
    }
}

// ================= gemm2 batched: scores (student) / E (teacher) =================
// grid.y = 512: blocks 0..255 -> Ss (mode1), 256..511 -> E + colsum (mode2).
#define STAGES 3
#define STAGE_BYTES 32768
__global__ void __launch_bounds__(256, 2)
k_gemm(const __nv_bfloat16* __restrict__ A, const __nv_bfloat16* __restrict__ B,
       __nv_bfloat16* __restrict__ Cs, __nv_bfloat16* __restrict__ Ce) {
    extern __shared__ char smem[];
    __shared__ float scp[2][128];

    int tid = threadIdx.x, wid = tid >> 5, lane = tid & 31;
    int by = blockIdx.y;
    int m0 = by * 128;                       // row in Zb / g_invn
    int n0 = blockIdx.x * 128;
    int teacher = (by >= 256);
    __nv_bfloat16* C = teacher ? (Ce + (size_t)(m0 - BB) * KK)
                               : (Cs + (size_t)m0 * KK);
    int wm = wid >> 2, wn = wid & 3;

    uint32_t s_base = smem_u32(smem);
    const int NT = KK >> 6;                  // 8

    int lrow = tid >> 3, lseg = tid & 7;
    const __nv_bfloat16* gA0 = A + (size_t)(m0 + lrow) * KK + lseg * 8;
    const __nv_bfloat16* gB0 = B + (size_t)(n0 + lrow) * KK + lseg * 8;
    auto load = [&](int kt, int st) {
        int kc = kt * 64;
        uint32_t sa = s_base + st * STAGE_BYTES;
#pragma unroll
        for (int p = 0; p < 4; p++) {
            uint32_t so = SWZ((lrow + p * 32) * 128 + lseg * 16);
            cp_async16(sa + so, gA0 + (size_t)p * 32 * KK + kc);
            cp_async16(sa + 16384 + so, gB0 + (size_t)p * 32 * KK + kc);
        }
        asm volatile("cp.async.commit_group;" ::: "memory");
    };

    uint32_t offA[4], offB[2];
    {
        int rA = (lane & 7) + ((lane >> 3) & 1) * 8;
        int sA = (lane >> 4) * 16;
#pragma unroll
        for (int im = 0; im < 4; im++) {
            int row = wm * 64 + im * 16 + rA;
            offA[im] = (uint32_t)(row * 128) | (uint32_t)(sA ^ ((row & 7) << 4));
        }
        int rB = (lane & 7) + ((lane >> 4) & 1) * 8;
        int sB = ((lane >> 3) & 1) * 16;
#pragma unroll
        for (int j = 0; j < 2; j++) {
            int row = wn * 32 + j * 16 + rB;
            offB[j] = 16384u + ((uint32_t)(row * 128) |
                                (uint32_t)(sB ^ ((row & 7) << 4)));
        }
    }

    float acc[4][4][4];
#pragma unroll
    for (int i = 0; i < 4; i++)
#pragma unroll
        for (int j = 0; j < 4; j++)
#pragma unroll
            for (int k = 0; k < 4; k++) acc[i][j][k] = 0.0f;

    load(0, 0);
    load(1, 1);

    for (int kt = 0; kt < NT; kt++) {
        asm volatile("cp.async.wait_group 1;" ::: "memory");
        __syncthreads();
        uint32_t sb = s_base + (uint32_t)(kt % 3) * STAGE_BYTES;
#pragma unroll
        for (int ks = 0; ks < 4; ks++) {
            uint32_t kx = (uint32_t)(ks << 5);
            uint32_t a[4][4], b[2][4];
#pragma unroll
            for (int im = 0; im < 4; im++) ldsm_x4(a[im], sb + (offA[im] ^ kx));
#pragma unroll
            for (int j = 0; j < 2; j++) ldsm_x4(b[j], sb + (offB[j] ^ kx));
#pragma unroll
            for (int im = 0; im < 4; im++)
#pragma unroll
                for (int j = 0; j < 2; j++) {
                    mma16816(acc[im][j * 2 + 0], a[im], b[j][0], b[j][1]);
                    mma16816(acc[im][j * 2 + 1], a[im], b[j][2], b[j][3]);
                }
        }
        if (kt + 2 < NT) load(kt + 2, (kt + 2) % 3);
        else asm volatile("cp.async.commit_group;" ::: "memory");
    }

    float ce0[4] = {0, 0, 0, 0}, ce1[4] = {0, 0, 0, 0};
#pragma unroll
    for (int im = 0; im < 4; im++) {
        int m = m0 + wm * 64 + im * 16 + (lane >> 2);
        int ml = wm * 64 + im * 16 + (lane >> 2);
        float i0 = g_invn[m], i1 = g_invn[m + 8];
#pragma unroll
        for (int jn = 0; jn < 4; jn++) {
            int n = n0 + wn * 32 + jn * 8 + (lane & 3) * 2;
            float c0 = acc[im][jn][0] * i0, c1 = acc[im][jn][1] * i0;
            float c2 = acc[im][jn][2] * i1, c3 = acc[im][jn][3] * i1;
            if (teacher) {
                c0 = fexp((c0 - 1.0f) * INV_T);
                c1 = fexp((c1 - 1.0f) * INV_T);
                c2 = fexp((c2 - 1.0f) * INV_T);
                c3 = fexp((c3 - 1.0f) * INV_T);
                ce0[jn] += c0 + c2;
                ce1[jn] += c1 + c3;
            }
            *(__nv_bfloat162*)(C + (size_t)ml * KK + n) = pack2(c0, c1);
            *(__nv_bfloat162*)(C + (size_t)(ml + 8) * KK + n) = pack2(c2, c3);
        }
    }
    if (teacher) {
#pragma unroll
        for (int jn = 0; jn < 4; jn++) {
#pragma unroll
            for (int o = 4; o < 32; o <<= 1) {
                ce0[jn] += __shfl_xor_sync(0xffffffffu, ce0[jn], o);
                ce1[jn] += __shfl_xor_sync(0xffffffffu, ce1[jn], o);
            }
        }
        if (lane < 4) {
#pragma unroll
            for (int jn = 0; jn < 4; jn++) {
                scp[wm][wn * 32 + jn * 8 + lane * 2 + 0] = ce0[jn];
                scp[wm][wn * 32 + jn * 8 + lane * 2 + 1] = ce1[jn];
            }
        }
        __syncthreads();
        if (tid < 128)
            atomicAdd(&g_R[n0 + tid], scp[0][tid] + scp[1][tid]);
    }
}

// ---------------- alpha_k = S / (K * R_k), reset R -----------------------------------
__global__ void k_alpha(int first) {
    int t = threadIdx.x;           // 512
    float Rk = g_R[t];
    __shared__ float sm[512];
    float S;
    if (first) {
        sm[t] = Rk;
        __syncthreads();
        for (int o = 256; o > 0; o >>= 1) {
            if (t < o) sm[t] += sm[t + o];
            __syncthreads();
        }
        S = sm[0];
        if (t == 0) g_S = S;
    } else {
        S = g_S;
    }
    g_alpha[t] = S / (512.0f * Rk);
    g_R[t] = 0.0f;
}

// ---------------- fused sinkhorn iteration ------------------------------------------
__global__ void k_rcpass() {
    int wid = threadIdx.x >> 5, lane = threadIdx.x & 31;
    __shared__ float sc[8][512];

    float al[16];
    const float* ap = g_alpha + lane * 16;
#pragma unroll
    for (int j = 0; j < 16; j++) al[j] = ap[j];
    float S = g_S;

    float colp[16];
#pragma unroll
    for (int j = 0; j < 16; j++) colp[j] = 0.0f;

    int row0 = blockIdx.x * 256 + wid * 32;
    for (int r = 0; r < 32; r++) {
        int row = row0 + r;
        const uint4* pe = (const uint4*)(g_E + (size_t)row * KK + lane * 16);
        uint4 u0 = pe[0], u1 = pe[1];
        float ev[16];
        {
            __nv_bfloat162* h0 = (__nv_bfloat162*)&u0;
            __nv_bfloat162* h1 = (__nv_bfloat162*)&u1;
#pragma unroll
            for (int k = 0; k < 4; k++) {
                float2 f0 = __bfloat1622float2(h0[k]);
                float2 f1 = __bfloat1622float2(h1[k]);
                ev[k * 2 + 0] = f0.x; ev[k * 2 + 1] = f0.y;
                ev[8 + k * 2 + 0] = f1.x; ev[8 + k * 2 + 1] = f1.y;
            }
        }
        float dot = 0.0f;
#pragma unroll
        for (int j = 0; j < 16; j++) dot = fmaf(ev[j], al[j], dot);
#pragma unroll
        for (int o = 16; o > 0; o >>= 1) dot += __shfl_xor_sync(0xffffffffu, dot, o);
        float beta = S / (32768.0f * dot);
#pragma unroll
        for (int j = 0; j < 16; j++) colp[j] = fmaf(ev[j], beta, colp[j]);
    }
#pragma unroll
    for (int j = 0; j < 16; j++) sc[wid][lane * 16 + j] = colp[j];
    __syncthreads();
    for (int c = threadIdx.x; c < 512; c += 256) {
        float sum = sc[0][c] + sc[1][c] + sc[2][c] + sc[3][c]
                  + sc[4][c] + sc[5][c] + sc[6][c] + sc[7][c];
        atomicAdd(&g_R[c], sum);
    }
}

// ---------------- fused lse + loss ----------------------------------------------------
__global__ void k_loss() {
    int wid = threadIdx.x >> 5, lane = threadIdx.x & 31;
    __shared__ float sl[8];

    float al[16];
    const float* ap = g_alpha + lane * 16;
#pragma unroll
    for (int j = 0; j < 16; j++) al[j] = ap[j];

    float lacc = 0.0f;
    int row0 = blockIdx.x * 64 + wid * 8;
    for (int r = 0; r < 8; r++) {
        int row = row0 + r;
        const uint4* pe = (const uint4*)(g_E + (size_t)row * KK + lane * 16);
        const uint4* ps = (const uint4*)(g_Ss + (size_t)row * KK + lane * 16);
        uint4 ue0 = pe[0], ue1 = pe[1], us0 = ps[0], us1 = ps[1];
        float ev[16], v[16];
        {
            __nv_bfloat162* he0 = (__nv_bfloat162*)&ue0;
            __nv_bfloat162* he1 = (__nv_bfloat162*)&ue1;
            __nv_bfloat162* hs0 = (__nv_bfloat162*)&us0;
            __nv_bfloat162* hs1 = (__nv_bfloat162*)&us1;
#pragma unroll
            for (int k = 0; k < 4; k++) {
                float2 f0 = __bfloat1622float2(he0[k]);
                float2 f1 = __bfloat1622float2(he1[k]);
                ev[k * 2] = f0.x; ev[k * 2 + 1] = f0.y;
                ev[8 + k * 2] = f1.x; ev[8 + k * 2 + 1] = f1.y;
                float2 g0 = __bfloat1622float2(hs0[k]);
                float2 g1 = __bfloat1622float2(hs1[k]);
                v[k * 2] = g0.x * INV_T; v[k * 2 + 1] = g0.y * INV_T;
                v[8 + k * 2] = g1.x * INV_T; v[8 + k * 2 + 1] = g1.y * INV_T;
            }
        }
        float mx = v[0];
#pragma unroll
        for (int j = 1; j < 16; j++) mx = fmaxf(mx, v[j]);
#pragma unroll
        for (int o = 16; o > 0; o >>= 1)
            mx = fmaxf(mx, __shfl_xor_sync(0xffffffffu, mx, o));
        float se = 0.0f, C = 0.0f, Acc = 0.0f;
#pragma unroll
        for (int j = 0; j < 16; j++) {
            se += fexp(v[j] - mx);
            float q = ev[j] * al[j];
            C += q;
            Acc = fmaf(q, v[j], Acc);
        }
#pragma unroll
        for (int o = 16; o > 0; o >>= 1) {
            se += __shfl_xor_sync(0xffffffffu, se, o);
            C += __shfl_xor_sync(0xffffffffu, C, o);
            Acc += __shfl_xor_sync(0xffffffffu, Acc, o);
        }
        float lse = mx + logf(se);
        lacc += -(Acc - lse * C) / C;
    }
    if (lane == 0) sl[wid] = lacc;
    __syncthreads();
    if (threadIdx.x == 0) {
        float b = sl[0] + sl[1] + sl[2] + sl[3] + sl[4] + sl[5] + sl[6] + sl[7];
        atomicAdd(&g_loss, b);
    }
}

__global__ void k_final(float* __restrict__ out) {
    out[0] = g_loss * (1.0f / 32768.0f);
}

// ---------------- launch ---------------------------------------------------------------
#define GEMM_SMEM (STAGES * STAGE_BYTES)

extern "C" void kernel_launch(void* const* d_in, const int* in_sizes, int n_in,
                              void* d_out, int out_size) {
    const float* s = nullptr;
    const float* t = nullptr;
    const float* W_net = nullptr;
    const float* W_proto = nullptr;
    for (int i = 0; i < n_in; i++) {
        long long sz = in_sizes[i];
        if (sz == (long long)BB * DD) {
            if (!s) s = (const float*)d_in[i];
            else if (!t) t = (const float*)d_in[i];
        } else if (sz == (long long)KK * DD) {
            W_net = (const float*)d_in[i];
        } else if (sz == (long long)KK * KK) {
            W_proto = (const float*)d_in[i];
        }
    }
    float* out = (float*)d_out;

    __nv_bfloat16 *Ss, *E, *Zb, *W, *Cn;
    cudaGetSymbolAddress((void**)&Ss, g_Ss);
    cudaGetSymbolAddress((void**)&E, g_E);
    cudaGetSymbolAddress((void**)&Zb, g_Zb);
    cudaGetSymbolAddress((void**)&W, g_W);
    cudaGetSymbolAddress((void**)&Cn, g_Cn);

    cudaFuncSetAttribute(k_gemm1f, cudaFuncAttributeMaxDynamicSharedMemorySize, G1_SMEM);
    cudaFuncSetAttribute(k_gemm, cudaFuncAttributeMaxDynamicSharedMemorySize, GEMM_SMEM);

    dim3 gg1(KK / 128, 2 * BB / 128);   // (4, 512) batched s+t
    dim3 gg2(KK / 128, 2 * BB / 128);   // (4, 512) batched student+teacher

    k_init<<<2 * BB / 512, 512>>>();
    k_proto<<<KK, 128>>>(W_proto);
    k_conv<<<512, 256>>>(W_net, W, (KK * DD) / 4);

    // batched: Zb[0:B)=s@W^T, Zb[B:2B)=t@W^T (+ row sumsq); invn; scores/E
    k_gemm1f<<<gg1, 256, G1_SMEM>>>(s, t, W, Zb);
    k_inv<<<2 * BB / 256, 256>>>();
    k_gemm<<<gg2, 256, GEMM_SMEM>>>(Zb, Cn, Ss, E);

    // sinkhorn (factor form, fused row+col passes)
    k_alpha<<<1, 512>>>(1);
    k_rcpass<<<128, 256>>>();
    k_alpha<<<1, 512>>>(0);
    k_rcpass<<<128, 256>>>();
    k_alpha<<<1, 512>>>(0);

    // fused lse + loss
    k_loss<<<512, 256>>>();
    k_final<<<1, 1>>>(out);
}

// round 13
// speedup vs baseline: 1.5469x; 1.0196x over previous
#include <cuda_runtime.h>
#include <cuda_bf16.h>
#include <math.h>
#include <stdint.h>

#define BB 32768
#define DD 1024
#define KK 512
#define INV_T 10.0f

// ---------------- scratch (static device globals) ----------------------------
__device__ __align__(16) __nv_bfloat16 g_Ss[16777216];   // scores_s bf16
__device__ __align__(16) __nv_bfloat16 g_E[16777216];    // E bf16
__device__ __align__(16) __nv_bfloat16 g_Zb[33554432];   // Z bf16 (s rows 0..32767, t rows 32768..65535)
__device__ __align__(16) __nv_bfloat16 g_W[524288];      // W_net bf16
__device__ __align__(16) __nv_bfloat16 g_Cn[262144];     // normalized protos bf16
__device__ float g_ss[2 * BB];      // row sumsq of Z (both branches)
__device__ float g_R[KK];
__device__ float g_alpha[KK];
__device__ float g_S;
__device__ float g_loss;

// ---------------- helpers ------------------------------------------------------
__device__ __forceinline__ uint32_t smem_u32(const void* p) {
    uint32_t a;
    asm("{ .reg .u64 t; cvta.to.shared.u64 t, %1; cvt.u32.u64 %0, t; }"
        : "=r"(a) : "l"(p));
    return a;
}
__device__ __forceinline__ void cp_async16(uint32_t saddr, const void* g) {
    asm volatile("cp.async.cg.shared.global [%0], [%1], 16;"
                 :: "r"(saddr), "l"(g) : "memory");
}
__device__ __forceinline__ void ldsm_x4(uint32_t* r, uint32_t addr) {
    asm volatile("ldmatrix.sync.aligned.m8n8.x4.shared.b16 {%0,%1,%2,%3}, [%4];"
                 : "=r"(r[0]), "=r"(r[1]), "=r"(r[2]), "=r"(r[3]) : "r"(addr));
}
__device__ __forceinline__ void mma16816(float* c, const uint32_t* a,
                                         uint32_t b0, uint32_t b1) {
    asm volatile(
        "mma.sync.aligned.m16n8k16.row.col.f32.bf16.bf16.f32 "
        "{%0,%1,%2,%3}, {%4,%5,%6,%7}, {%8,%9}, {%0,%1,%2,%3};"
        : "+f"(c[0]), "+f"(c[1]), "+f"(c[2]), "+f"(c[3])
        : "r"(a[0]), "r"(a[1]), "r"(a[2]), "r"(a[3]), "r"(b0), "r"(b1));
}
#define SWZ(o) ((o) ^ (((o) >> 3) & 0x70))

// fast e^x on the FMA pipe (exp2-based, degree-6 poly, rel err ~6e-8)
__device__ __forceinline__ float fexp(float x) {
    float y = x * 1.4426950408889634f;
    float t = y + 12582912.0f;
    int e = __float_as_int(t) - 0x4B400000;
    float f = y - (t - 12582912.0f);
    float p = 1.5403530e-4f;
    p = fmaf(p, f, 1.3333558e-3f);
    p = fmaf(p, f, 9.6181291e-3f);
    p = fmaf(p, f, 5.5504109e-2f);
    p = fmaf(p, f, 2.4022651e-1f);
    p = fmaf(p, f, 6.9314718e-1f);
    p = fmaf(p, f, 1.0f);
    return p * __int_as_float((e + 127) << 23);
}

__device__ __forceinline__ __nv_bfloat162 pack2(float a, float b) {
    return __halves2bfloat162(__float2bfloat16(a), __float2bfloat16(b));
}

// ---------------- init ----------------------------------------------------------
__global__ void k_init() {
    int i = blockIdx.x * blockDim.x + threadIdx.x;     // 65536 threads
    g_ss[i] = 0.0f;
    if (i < KK) g_R[i] = 0.0f;
    if (i == 0) g_loss = 0.0f;
}

// ---------------- Cn = l2norm rows of W_proto -> bf16 ---------------------------
__global__ void k_proto(const float* __restrict__ W) {
    int row = blockIdx.x;
    int t = threadIdx.x;
    float4 v = ((const float4*)(W + (size_t)row * KK))[t];
    float s = v.x * v.x + v.y * v.y + v.z * v.z + v.w * v.w;
    __shared__ float sm[128];
    sm[t] = s;
    __syncthreads();
    for (int o = 64; o > 0; o >>= 1) {
        if (t < o) sm[t] += sm[t + o];
        __syncthreads();
    }
    float inv = rsqrtf(sm[0]);
    __nv_bfloat162* hp = (__nv_bfloat162*)(g_Cn + (size_t)row * KK + t * 4);
    hp[0] = pack2(v.x * inv, v.y * inv);
    hp[1] = pack2(v.z * inv, v.w * inv);
}

// ---------------- f32 -> bf16 (W_net only; tiny) ----------------------------------
__global__ void k_conv(const float* __restrict__ x, __nv_bfloat16* __restrict__ hd,
                       int n4) {
    int i = blockIdx.x * blockDim.x + threadIdx.x;
    int stride = gridDim.x * blockDim.x;
    for (; i < n4; i += stride) {
        float4 v = ((const float4*)x)[i];
        __nv_bfloat162* hp = (__nv_bfloat162*)(hd + (size_t)i * 4);
        hp[0] = pack2(v.x, v.y);
        hp[1] = pack2(v.z, v.w);
    }
}

// ================= gemm1 batched: Zb[0:B) = s@W^T, Zb[B:2B) = t@W^T ==============
#define G1_ABF 0
#define G1_BT 32768
#define G1_SMEM 65536
__global__ void __launch_bounds__(256, 2)
k_gemm1f(const float* __restrict__ S, const float* __restrict__ T,
         const __nv_bfloat16* __restrict__ B, __nv_bfloat16* __restrict__ C) {
    extern __shared__ char smem[];
    const int Kd = DD;          // 1024
    const int NT = Kd >> 6;     // 16 k-tiles

    int tid = threadIdx.x, wid = tid >> 5, lane = tid & 31;
    int by = blockIdx.y;
    const float* A = (by < 256) ? S : T;
    int am0 = (by & 255) * 128;
    int m0 = by * 128;
    int n0 = blockIdx.x * 128;
    int wm = wid >> 2, wn = wid & 3;

    uint32_t s_base = smem_u32(smem);

    int lrow = tid >> 3, lseg = tid & 7;
    const float* gA0 = A + (size_t)(am0 + lrow) * Kd + lseg * 4;
    const __nv_bfloat16* gB0 = B + (size_t)(n0 + lrow) * Kd + lseg * 8;

    auto loadB = [&](int kt, int st) {
        uint32_t sa = s_base + G1_BT + (uint32_t)st * 16384;
        int kc = kt * 64;
#pragma unroll
        for (int p = 0; p < 4; p++) {
            uint32_t so = SWZ((lrow + p * 32) * 128 + lseg * 16);
            cp_async16(sa + so, gB0 + (size_t)p * 32 * Kd + kc);
        }
        asm volatile("cp.async.commit_group;" ::: "memory");
    };

    float4 fb[4];
    auto ldgA = [&](int kt, int h) {
#pragma unroll
        for (int p = 0; p < 4; p++)
            fb[p] = *(const float4*)(gA0 + (size_t)p * 32 * Kd + kt * 64 + h * 32);
    };
    uint32_t stsAddr[4][2];
#pragma unroll
    for (int p = 0; p < 4; p++)
#pragma unroll
        for (int h = 0; h < 2; h++)
            stsAddr[p][h] = SWZ((uint32_t)((lrow + p * 32) * 128 + lseg * 8 + h * 64));
    auto stsA = [&](int st, int h) {
        uint32_t ab = s_base + G1_ABF + (uint32_t)st * 16384;
#pragma unroll
        for (int p = 0; p < 4; p++) {
            __nv_bfloat162 q0 = pack2(fb[p].x, fb[p].y);
            __nv_bfloat162 q1 = pack2(fb[p].z, fb[p].w);
            asm volatile("st.shared.v2.b32 [%0], {%1,%2};"
                         :: "r"(ab + stsAddr[p][h]),
                            "r"(*(uint32_t*)&q0), "r"(*(uint32_t*)&q1) : "memory");
        }
    };

    uint32_t offA[4], offB[2];
    {
        int rA = (lane & 7) + ((lane >> 3) & 1) * 8;
        int sA = (lane >> 4) * 16;
#pragma unroll
        for (int im = 0; im < 4; im++) {
            int row = wm * 64 + im * 16 + rA;
            offA[im] = (uint32_t)(row * 128) | (uint32_t)(sA ^ ((row & 7) << 4));
        }
        int rB = (lane & 7) + ((lane >> 4) & 1) * 8;
        int sB = ((lane >> 3) & 1) * 16;
#pragma unroll
        for (int j = 0; j < 2; j++) {
            int row = wn * 32 + j * 16 + rB;
            offB[j] = (uint32_t)(row * 128) | (uint32_t)(sB ^ ((row & 7) << 4));
        }
    }

    float acc[4][4][4];
#pragma unroll
    for (int i = 0; i < 4; i++)
#pragma unroll
        for (int j = 0; j < 4; j++)
#pragma unroll
            for (int k = 0; k < 4; k++) acc[i][j][k] = 0.0f;

    loadB(0, 0);
    ldgA(0, 0); stsA(0, 0);
    ldgA(0, 1); stsA(0, 1);
    asm volatile("cp.async.wait_group 0;" ::: "memory");
    __syncthreads();

    for (int kt = 0; kt < NT; kt++) {
        int st = kt & 1;
        bool more = (kt + 1 < NT);
        if (more) {
            loadB(kt + 1, st ^ 1);
            ldgA(kt + 1, 0);
        }
        uint32_t sbA = s_base + G1_ABF + (uint32_t)st * 16384;
        uint32_t sbB = s_base + G1_BT + (uint32_t)st * 16384;
#pragma unroll
        for (int ks = 0; ks < 2; ks++) {
            uint32_t kx = (uint32_t)(ks << 5);
            uint32_t a[4][4], b[2][4];
#pragma unroll
            for (int im = 0; im < 4; im++) ldsm_x4(a[im], sbA + (offA[im] ^ kx));
#pragma unroll
            for (int j = 0; j < 2; j++) ldsm_x4(b[j], sbB + (offB[j] ^ kx));
#pragma unroll
            for (int im = 0; im < 4; im++)
#pragma unroll
                for (int j = 0; j < 2; j++) {
                    mma16816(acc[im][j * 2 + 0], a[im], b[j][0], b[j][1]);
                    mma16816(acc[im][j * 2 + 1], a[im], b[j][2], b[j][3]);
                }
        }
        if (more) {
            stsA(st ^ 1, 0);
            ldgA(kt + 1, 1);
        }
#pragma unroll
        for (int ks = 2; ks < 4; ks++) {
            uint32_t kx = (uint32_t)(ks << 5);
            uint32_t a[4][4], b[2][4];
#pragma unroll
            for (int im = 0; im < 4; im++) ldsm_x4(a[im], sbA + (offA[im] ^ kx));
#pragma unroll
            for (int j = 0; j < 2; j++) ldsm_x4(b[j], sbB + (offB[j] ^ kx));
#pragma unroll
            for (int im = 0; im < 4; im++)
#pragma unroll
                for (int j = 0; j < 2; j++) {
                    mma16816(acc[im][j * 2 + 0], a[im], b[j][0], b[j][1]);
                    mma16816(acc[im][j * 2 + 1], a[im], b[j][2], b[j][3]);
                }
        }
        if (more) {
            stsA(st ^ 1, 1);
            asm volatile("cp.async.wait_group 0;" ::: "memory");
        }
        __syncthreads();
    }

    // ---- epilogue: bf16 out + row sumsq ----
#pragma unroll
    for (int im = 0; im < 4; im++) {
        int m = m0 + wm * 64 + im * 16 + (lane >> 2);
        float s0 = 0.0f, s1 = 0.0f;
#pragma unroll
        for (int jn = 0; jn < 4; jn++) {
            int n = n0 + wn * 32 + jn * 8 + (lane & 3) * 2;
            float c0 = acc[im][jn][0], c1 = acc[im][jn][1];
            float c2 = acc[im][jn][2], c3 = acc[im][jn][3];
            s0 += c0 * c0 + c1 * c1;
            s1 += c2 * c2 + c3 * c3;
            *(__nv_bfloat162*)(C + (size_t)m * KK + n) = pack2(c0, c1);
            *(__nv_bfloat162*)(C + (size_t)(m + 8) * KK + n) = pack2(c2, c3);
        }
        s0 += __shfl_xor_sync(0xffffffffu, s0, 1);
        s0 += __shfl_xor_sync(0xffffffffu, s0, 2);
        s1 += __shfl_xor_sync(0xffffffffu, s1, 1);
        s1 += __shfl_xor_sync(0xffffffffu, s1, 2);
        if ((lane & 3) == 0) {
            atomicAdd(&g_ss[m], s0);
            atomicAdd(&g_ss[m + 8], s1);
        }
    }
}

// ================= gemm2 batched: scores (student) / E (teacher) =================
// invn computed inline from g_ss (k_inv removed).
#define STAGES 3
#define STAGE_BYTES 32768
__global__ void __launch_bounds__(256, 2)
k_gemm(const __nv_bfloat16* __restrict__ A, const __nv_bfloat16* __restrict__ B,
       __nv_bfloat16* __restrict__ Cs, __nv_bfloat16* __restrict__ Ce) {
    extern __shared__ char smem[];
    __shared__ float scp[2][128];

    int tid = threadIdx.x, wid = tid >> 5, lane = tid & 31;
    int by = blockIdx.y;
    int m0 = by * 128;
    int n0 = blockIdx.x * 128;
    int teacher = (by >= 256);
    __nv_bfloat16* C = teacher ? (Ce + (size_t)(m0 - BB) * KK)
                               : (Cs + (size_t)m0 * KK);
    int wm = wid >> 2, wn = wid & 3;

    uint32_t s_base = smem_u32(smem);
    const int NT = KK >> 6;                  // 8

    int lrow = tid >> 3, lseg = tid & 7;
    const __nv_bfloat16* gA0 = A + (size_t)(m0 + lrow) * KK + lseg * 8;
    const __nv_bfloat16* gB0 = B + (size_t)(n0 + lrow) * KK + lseg * 8;
    auto load = [&](int kt, int st) {
        int kc = kt * 64;
        uint32_t sa = s_base + st * STAGE_BYTES;
#pragma unroll
        for (int p = 0; p < 4; p++) {
            uint32_t so = SWZ((lrow + p * 32) * 128 + lseg * 16);
            cp_async16(sa + so, gA0 + (size_t)p * 32 * KK + kc);
            cp_async16(sa + 16384 + so, gB0 + (size_t)p * 32 * KK + kc);
        }
        asm volatile("cp.async.commit_group;" ::: "memory");
    };

    uint32_t offA[4], offB[2];
    {
        int rA = (lane & 7) + ((lane >> 3) & 1) * 8;
        int sA = (lane >> 4) * 16;
#pragma unroll
        for (int im = 0; im < 4; im++) {
            int row = wm * 64 + im * 16 + rA;
            offA[im] = (uint32_t)(row * 128) | (uint32_t)(sA ^ ((row & 7) << 4));
        }
        int rB = (lane & 7) + ((lane >> 4) & 1) * 8;
        int sB = ((lane >> 3) & 1) * 16;
#pragma unroll
        for (int j = 0; j < 2; j++) {
            int row = wn * 32 + j * 16 + rB;
            offB[j] = 16384u + ((uint32_t)(row * 128) |
                                (uint32_t)(sB ^ ((row & 7) << 4)));
        }
    }

    float acc[4][4][4];
#pragma unroll
    for (int i = 0; i < 4; i++)
#pragma unroll
        for (int j = 0; j < 4; j++)
#pragma unroll
            for (int k = 0; k < 4; k++) acc[i][j][k] = 0.0f;

    load(0, 0);
    load(1, 1);

    for (int kt = 0; kt < NT; kt++) {
        asm volatile("cp.async.wait_group 1;" ::: "memory");
        __syncthreads();
        uint32_t sb = s_base + (uint32_t)(kt % 3) * STAGE_BYTES;
#pragma unroll
        for (int ks = 0; ks < 4; ks++) {
            uint32_t kx = (uint32_t)(ks << 5);
            uint32_t a[4][4], b[2][4];
#pragma unroll
            for (int im = 0; im < 4; im++) ldsm_x4(a[im], sb + (offA[im] ^ kx));
#pragma unroll
            for (int j = 0; j < 2; j++) ldsm_x4(b[j], sb + (offB[j] ^ kx));
#pragma unroll
            for (int im = 0; im < 4; im++)
#pragma unroll
                for (int j = 0; j < 2; j++) {
                    mma16816(acc[im][j * 2 + 0], a[im], b[j][0], b[j][1]);
                    mma16816(acc[im][j * 2 + 1], a[im], b[j][2], b[j][3]);
                }
        }
        if (kt + 2 < NT) load(kt + 2, (kt + 2) % 3);
        else asm volatile("cp.async.commit_group;" ::: "memory");
    }

    float ce0[4] = {0, 0, 0, 0}, ce1[4] = {0, 0, 0, 0};
#pragma unroll
    for (int im = 0; im < 4; im++) {
        int m = m0 + wm * 64 + im * 16 + (lane >> 2);
        int ml = wm * 64 + im * 16 + (lane >> 2);
        float i0 = rsqrtf(g_ss[m]), i1 = rsqrtf(g_ss[m + 8]);
#pragma unroll
        for (int jn = 0; jn < 4; jn++) {
            int n = n0 + wn * 32 + jn * 8 + (lane & 3) * 2;
            float c0 = acc[im][jn][0] * i0, c1 = acc[im][jn][1] * i0;
            float c2 = acc[im][jn][2] * i1, c3 = acc[im][jn][3] * i1;
            if (teacher) {
                c0 = fexp((c0 - 1.0f) * INV_T);
                c1 = fexp((c1 - 1.0f) * INV_T);
                c2 = fexp((c2 - 1.0f) * INV_T);
                c3 = fexp((c3 - 1.0f) * INV_T);
                ce0[jn] += c0 + c2;
                ce1[jn] += c1 + c3;
            }
            *(__nv_bfloat162*)(C + (size_t)ml * KK + n) = pack2(c0, c1);
            *(__nv_bfloat162*)(C + (size_t)(ml + 8) * KK + n) = pack2(c2, c3);
        }
    }
    if (teacher) {
#pragma unroll
        for (int jn = 0; jn < 4; jn++) {
#pragma unroll
            for (int o = 4; o < 32; o <<= 1) {
                ce0[jn] += __shfl_xor_sync(0xffffffffu, ce0[jn], o);
                ce1[jn] += __shfl_xor_sync(0xffffffffu, ce1[jn], o);
            }
        }
        if (lane < 4) {
#pragma unroll
            for (int jn = 0; jn < 4; jn++) {
                scp[wm][wn * 32 + jn * 8 + lane * 2 + 0] = ce0[jn];
                scp[wm][wn * 32 + jn * 8 + lane * 2 + 1] = ce1[jn];
            }
        }
        __syncthreads();
        if (tid < 128)
            atomicAdd(&g_R[n0 + tid], scp[0][tid] + scp[1][tid]);
    }
}

// ---------------- alpha_k = S / (K * R_k), reset R -----------------------------------
__global__ void k_alpha(int first) {
    int t = threadIdx.x;           // 512
    float Rk = g_R[t];
    __shared__ float sm[512];
    float S;
    if (first) {
        sm[t] = Rk;
        __syncthreads();
        for (int o = 256; o > 0; o >>= 1) {
            if (t < o) sm[t] += sm[t + o];
            __syncthreads();
        }
        S = sm[0];
        if (t == 0) g_S = S;
    } else {
        S = g_S;
    }
    g_alpha[t] = S / (512.0f * Rk);
    g_R[t] = 0.0f;
}

// ---------------- fused sinkhorn iteration (512 blocks, 8 rows/warp) -----------------
__global__ void k_rcpass() {
    int wid = threadIdx.x >> 5, lane = threadIdx.x & 31;
    __shared__ float sc[8][512];

    float al[16];
    const float* ap = g_alpha + lane * 16;
#pragma unroll
    for (int j = 0; j < 16; j++) al[j] = ap[j];
    float S = g_S;

    float colp[16];
#pragma unroll
    for (int j = 0; j < 16; j++) colp[j] = 0.0f;

    int row0 = blockIdx.x * 64 + wid * 8;
#pragma unroll
    for (int r = 0; r < 8; r++) {
        int row = row0 + r;
        const uint4* pe = (const uint4*)(g_E + (size_t)row * KK + lane * 16);
        uint4 u0 = pe[0], u1 = pe[1];
        float ev[16];
        {
            __nv_bfloat162* h0 = (__nv_bfloat162*)&u0;
            __nv_bfloat162* h1 = (__nv_bfloat162*)&u1;
#pragma unroll
            for (int k = 0; k < 4; k++) {
                float2 f0 = __bfloat1622float2(h0[k]);
                float2 f1 = __bfloat1622float2(h1[k]);
                ev[k * 2 + 0] = f0.x; ev[k * 2 + 1] = f0.y;
                ev[8 + k * 2 + 0] = f1.x; ev[8 + k * 2 + 1] = f1.y;
            }
        }
        float dot = 0.0f;
#pragma unroll
        for (int j = 0; j < 16; j++) dot = fmaf(ev[j], al[j], dot);
#pragma unroll
        for (int o = 16; o > 0; o >>= 1) dot += __shfl_xor_sync(0xffffffffu, dot, o);
        float beta = S / (32768.0f * dot);
#pragma unroll
        for (int j = 0; j < 16; j++) colp[j] = fmaf(ev[j], beta, colp[j]);
    }
#pragma unroll
    for (int j = 0; j < 16; j++) sc[wid][lane * 16 + j] = colp[j];
    __syncthreads();
    for (int c = threadIdx.x; c < 512; c += 256) {
        float sum = sc[0][c] + sc[1][c] + sc[2][c] + sc[3][c]
                  + sc[4][c] + sc[5][c] + sc[6][c] + sc[7][c];
        atomicAdd(&g_R[c], sum);
    }
}

// ---------------- fused lse + loss (alpha derived from g_R in-register) ---------------
__global__ void k_loss() {
    int wid = threadIdx.x >> 5, lane = threadIdx.x & 31;
    __shared__ float sl[8];

    float S = g_S;
    float al[16];
    const float* rp = g_R + lane * 16;
#pragma unroll
    for (int j = 0; j < 16; j++) al[j] = S / (512.0f * rp[j]);

    float lacc = 0.0f;
    int row0 = blockIdx.x * 64 + wid * 8;
#pragma unroll
    for (int r = 0; r < 8; r++) {
        int row = row0 + r;
        const uint4* pe = (const uint4*)(g_E + (size_t)row * KK + lane * 16);
        const uint4* ps = (const uint4*)(g_Ss + (size_t)row * KK + lane * 16);
        uint4 ue0 = pe[0], ue1 = pe[1], us0 = ps[0], us1 = ps[1];
        float ev[16], v[16];
        {
            __nv_bfloat162* he0 = (__nv_bfloat162*)&ue0;
            __nv_bfloat162* he1 = (__nv_bfloat162*)&ue1;
            __nv_bfloat162* hs0 = (__nv_bfloat162*)&us0;
            __nv_bfloat162* hs1 = (__nv_bfloat162*)&us1;
#pragma unroll
            for (int k = 0; k < 4; k++) {
                float2 f0 = __bfloat1622float2(he0[k]);
                float2 f1 = __bfloat1622float2(he1[k]);
                ev[k * 2] = f0.x; ev[k * 2 + 1] = f0.y;
                ev[8 + k * 2] = f1.x; ev[8 + k * 2 + 1] = f1.y;
                float2 g0 = __bfloat1622float2(hs0[k]);
                float2 g1 = __bfloat1622float2(hs1[k]);
                v[k * 2] = g0.x * INV_T; v[k * 2 + 1] = g0.y * INV_T;
                v[8 + k * 2] = g1.x * INV_T; v[8 + k * 2 + 1] = g1.y * INV_T;
            }
        }
        float mx = v[0];
#pragma unroll
        for (int j = 1; j < 16; j++) mx = fmaxf(mx, v[j]);
#pragma unroll
        for (int o = 16; o > 0; o >>= 1)
            mx = fmaxf(mx, __shfl_xor_sync(0xffffffffu, mx, o));
        float se = 0.0f, C = 0.0f, Acc = 0.0f;
#pragma unroll
        for (int j = 0; j < 16; j++) {
            se += fexp(v[j] - mx);
            float q = ev[j] * al[j];
            C += q;
            Acc = fmaf(q, v[j], Acc);
        }
#pragma unroll
        for (int o = 16; o > 0; o >>= 1) {
            se += __shfl_xor_sync(0xffffffffu, se, o);
            C += __shfl_xor_sync(0xffffffffu, C, o);
            Acc += __shfl_xor_sync(0xffffffffu, Acc, o);
        }
        float lse = mx + logf(se);
        lacc += -(Acc - lse * C) / C;
    }
    if (lane == 0) sl[wid] = lacc;
    __syncthreads();
    if (threadIdx.x == 0) {
        float b = sl[0] + sl[1] + sl[2] + sl[3] + sl[4] + sl[5] + sl[6] + sl[7];
        atomicAdd(&g_loss, b);
    }
}

__global__ void k_final(float* __restrict__ out) {
    out[0] = g_loss * (1.0f / 32768.0f);
}

// ---------------- launch ---------------------------------------------------------------
#define GEMM_SMEM (STAGES * STAGE_BYTES)

extern "C" void kernel_launch(void* const* d_in, const int* in_sizes, int n_in,
                              void* d_out, int out_size) {
    const float* s = nullptr;
    const float* t = nullptr;
    const float* W_net = nullptr;
    const float* W_proto = nullptr;
    for (int i = 0; i < n_in; i++) {
        long long sz = in_sizes[i];
        if (sz == (long long)BB * DD) {
            if (!s) s = (const float*)d_in[i];
            else if (!t) t = (const float*)d_in[i];
        } else if (sz == (long long)KK * DD) {
            W_net = (const float*)d_in[i];
        } else if (sz == (long long)KK * KK) {
            W_proto = (const float*)d_in[i];
        }
    }
    float* out = (float*)d_out;

    __nv_bfloat16 *Ss, *E, *Zb, *W, *Cn;
    cudaGetSymbolAddress((void**)&Ss, g_Ss);
    cudaGetSymbolAddress((void**)&E, g_E);
    cudaGetSymbolAddress((void**)&Zb, g_Zb);
    cudaGetSymbolAddress((void**)&W, g_W);
    cudaGetSymbolAddress((void**)&Cn, g_Cn);

    cudaFuncSetAttribute(k_gemm1f, cudaFuncAttributeMaxDynamicSharedMemorySize, G1_SMEM);
    cudaFuncSetAttribute(k_gemm, cudaFuncAttributeMaxDynamicSharedMemorySize, GEMM_SMEM);

    dim3 gg(KK / 128, 2 * BB / 128);   // (4, 512) batched

    k_init<<<2 * BB / 512, 512>>>();
    k_proto<<<KK, 128>>>(W_proto);
    k_conv<<<512, 256>>>(W_net, W, (KK * DD) / 4);

    // batched: Zb[0:B)=s@W^T, Zb[B:2B)=t@W^T (+ row sumsq); scores/E (invn inline)
    k_gemm1f<<<gg, 256, G1_SMEM>>>(s, t, W, Zb);
    k_gemm<<<gg, 256, GEMM_SMEM>>>(Zb, Cn, Ss, E);

    // sinkhorn (factor form, fused row+col passes)
    k_alpha<<<1, 512>>>(1);
    k_rcpass<<<512, 256>>>();
    k_alpha<<<1, 512>>>(0);
    k_rcpass<<<512, 256>>>();
    // alpha3 folded into k_loss (reads g_R + g_S directly)

    // fused lse + loss
    k_loss<<<512, 256>>>();
    k_final<<<1, 1>>>(out);
}